// round 3
// baseline (speedup 1.0000x reference)
#include <cuda_runtime.h>
#include <cuda_bf16.h>

// Problem constants
#define BB   4
#define SS   2048
#define DD   1024
#define HH   16
#define DKK  64
#define MTOT (BB*SS)          // 8192 rows for all projections

// Scratch (no cudaMalloc allowed) — 4 x 32MB fp32
__device__ float g_Q [BB*SS*DD];
__device__ float g_K [BB*SS*DD];
__device__ float g_V [BB*SS*DD];
__device__ float g_AO[BB*SS*DD];

// ---------------------------------------------------------------------------
// GEMM: C[M,N] = A[M,K] @ W[N,K]^T + bias[N]
// BM=BN=128, BK=8, 256 threads, 8x8 per thread.
// ---------------------------------------------------------------------------
__global__ __launch_bounds__(256) void gemm_bias_kernel(
    const float* __restrict__ A, const float* __restrict__ W,
    const float* __restrict__ bias, float* __restrict__ C,
    int M, int N, int K)
{
    const int BM = 128, BN = 128, BK = 8;
    __shared__ float As[BK][BM + 4];
    __shared__ float Bs[BK][BN + 4];

    const int tid = threadIdx.x;
    const int tx = tid & 15;          // 0..15 -> n
    const int ty = tid >> 4;          // 0..15 -> m
    const int bm = blockIdx.y * BM;
    const int bn = blockIdx.x * BN;

    float acc[8][8];
#pragma unroll
    for (int i = 0; i < 8; i++)
#pragma unroll
        for (int j = 0; j < 8; j++) acc[i][j] = 0.f;

    // Load mapping: 256 threads, each one float4 from A and one from W per BK slab
    const int lrow = tid >> 1;          // 0..127
    const int lcol = (tid & 1) * 4;     // 0 or 4
    const float* Aptr = A + (size_t)(bm + lrow) * K + lcol;
    const float* Wptr = W + (size_t)(bn + lrow) * K + lcol;

    for (int k0 = 0; k0 < K; k0 += BK) {
        float4 av = *(const float4*)(Aptr + k0);
        float4 wv = *(const float4*)(Wptr + k0);
        As[lcol + 0][lrow] = av.x;  As[lcol + 1][lrow] = av.y;
        As[lcol + 2][lrow] = av.z;  As[lcol + 3][lrow] = av.w;
        Bs[lcol + 0][lrow] = wv.x;  Bs[lcol + 1][lrow] = wv.y;
        Bs[lcol + 2][lrow] = wv.z;  Bs[lcol + 3][lrow] = wv.w;
        __syncthreads();

#pragma unroll
        for (int k = 0; k < BK; k++) {
            float4 a0 = *(const float4*)&As[k][ty * 8];
            float4 a1 = *(const float4*)&As[k][ty * 8 + 4];
            float4 b0 = *(const float4*)&Bs[k][tx * 8];
            float4 b1 = *(const float4*)&Bs[k][tx * 8 + 4];
            float af[8] = {a0.x, a0.y, a0.z, a0.w, a1.x, a1.y, a1.z, a1.w};
            float bf[8] = {b0.x, b0.y, b0.z, b0.w, b1.x, b1.y, b1.z, b1.w};
#pragma unroll
            for (int i = 0; i < 8; i++)
#pragma unroll
                for (int j = 0; j < 8; j++)
                    acc[i][j] = fmaf(af[i], bf[j], acc[i][j]);
        }
        __syncthreads();
    }

#pragma unroll
    for (int i = 0; i < 8; i++) {
        const int row = bm + ty * 8 + i;
#pragma unroll
        for (int j = 0; j < 8; j += 4) {
            const int col = bn + tx * 8 + j;
            float4 v;
            v.x = acc[i][j + 0] + bias[col + 0];
            v.y = acc[i][j + 1] + bias[col + 1];
            v.z = acc[i][j + 2] + bias[col + 2];
            v.w = acc[i][j + 3] + bias[col + 3];
            *(float4*)(C + (size_t)row * N + col) = v;
        }
    }
}

// ---------------------------------------------------------------------------
// Flash attention: per block = one (b,h) and one 64-row Q tile.
// Online softmax, KV streamed in 64-row tiles. 256 threads, 4x4 per thread.
// Dynamic smem: Qs[d][m], Ks[d][n], Vs[n][d], Ps[m][n], each 64x68 floats.
// ---------------------------------------------------------------------------
#define AT_STRIDE 68
#define AT_TILE_FLOATS (64 * AT_STRIDE)
#define AT_SMEM_BYTES (4 * AT_TILE_FLOATS * 4)

__global__ __launch_bounds__(256) void attn_kernel(
    const float* __restrict__ Q, const float* __restrict__ K,
    const float* __restrict__ V, float* __restrict__ O)
{
    extern __shared__ float smem[];
    float* Qs = smem;                      // [d][m] transposed, Q pre-scaled
    float* Ks = Qs + AT_TILE_FLOATS;       // [d][n] transposed
    float* Vs = Ks + AT_TILE_FLOATS;       // [n][d]
    float* Ps = Vs + AT_TILE_FLOATS;       // [m][n]

    const int qt = blockIdx.x;             // 0..31
    const int h  = blockIdx.y;             // 0..15
    const int b  = blockIdx.z;             // 0..3
    const float scale = 0.125f;            // 1/sqrt(64)

    const int tid = threadIdx.x;
    const int tn = tid & 15;               // n / d group (4 cols)
    const int tm = tid >> 4;               // m group (4 rows)

    const size_t base = ((size_t)b * SS) * DD + (size_t)h * DKK;
    const float* Qp = Q + base + (size_t)(qt * 64) * DD;

    // Load + transpose + pre-scale Q tile
#pragma unroll
    for (int p = 0; p < 4; p++) {
        int idx = tid + p * 256;           // 0..1023 float4s
        int r  = idx >> 4;                 // row in tile
        int c4 = idx & 15;                 // float4 within row
        float4 v = *(const float4*)(Qp + (size_t)r * DD + c4 * 4);
        Qs[(c4 * 4 + 0) * AT_STRIDE + r] = v.x * scale;
        Qs[(c4 * 4 + 1) * AT_STRIDE + r] = v.y * scale;
        Qs[(c4 * 4 + 2) * AT_STRIDE + r] = v.z * scale;
        Qs[(c4 * 4 + 3) * AT_STRIDE + r] = v.w * scale;
    }

    float m_run[4], l_run[4], o[4][4];
#pragma unroll
    for (int i = 0; i < 4; i++) {
        m_run[i] = -1e30f; l_run[i] = 0.f;
#pragma unroll
        for (int j = 0; j < 4; j++) o[i][j] = 0.f;
    }

    for (int kt = 0; kt < SS / 64; kt++) {
        // Load K (transposed) and V (direct) tiles
        const float* Kp = K + base + (size_t)(kt * 64) * DD;
        const float* Vp = V + base + (size_t)(kt * 64) * DD;
        __syncthreads();   // make sure previous iteration's reads are done
#pragma unroll
        for (int p = 0; p < 4; p++) {
            int idx = tid + p * 256;
            int r  = idx >> 4;
            int c4 = idx & 15;
            float4 kv = *(const float4*)(Kp + (size_t)r * DD + c4 * 4);
            Ks[(c4 * 4 + 0) * AT_STRIDE + r] = kv.x;
            Ks[(c4 * 4 + 1) * AT_STRIDE + r] = kv.y;
            Ks[(c4 * 4 + 2) * AT_STRIDE + r] = kv.z;
            Ks[(c4 * 4 + 3) * AT_STRIDE + r] = kv.w;
            float4 vv = *(const float4*)(Vp + (size_t)r * DD + c4 * 4);
            *(float4*)&Vs[r * AT_STRIDE + c4 * 4] = vv;
        }
        __syncthreads();

        // S = Q K^T (4x4 per thread)
        float s[4][4];
#pragma unroll
        for (int i = 0; i < 4; i++)
#pragma unroll
            for (int j = 0; j < 4; j++) s[i][j] = 0.f;

#pragma unroll 8
        for (int d = 0; d < DKK; d++) {
            float4 qf = *(const float4*)&Qs[d * AT_STRIDE + tm * 4];
            float4 kf = *(const float4*)&Ks[d * AT_STRIDE + tn * 4];
            float qa[4] = {qf.x, qf.y, qf.z, qf.w};
            float ka[4] = {kf.x, kf.y, kf.z, kf.w};
#pragma unroll
            for (int i = 0; i < 4; i++)
#pragma unroll
                for (int j = 0; j < 4; j++)
                    s[i][j] = fmaf(qa[i], ka[j], s[i][j]);
        }

        // Online softmax per row (reduce across the 16 threads sharing tm)
#pragma unroll
        for (int i = 0; i < 4; i++) {
            float mx = fmaxf(fmaxf(s[i][0], s[i][1]), fmaxf(s[i][2], s[i][3]));
#pragma unroll
            for (int off = 8; off >= 1; off >>= 1)
                mx = fmaxf(mx, __shfl_xor_sync(0xffffffffu, mx, off));
            float mnew  = fmaxf(m_run[i], mx);
            float alpha = __expf(m_run[i] - mnew);
            m_run[i] = mnew;
            float psum = 0.f;
#pragma unroll
            for (int j = 0; j < 4; j++) {
                float p = __expf(s[i][j] - mnew);
                s[i][j] = p;
                psum += p;
            }
#pragma unroll
            for (int off = 8; off >= 1; off >>= 1)
                psum += __shfl_xor_sync(0xffffffffu, psum, off);
            l_run[i] = l_run[i] * alpha + psum;
#pragma unroll
            for (int j = 0; j < 4; j++) o[i][j] *= alpha;
            // Stage P to smem for the PV GEMM
            *(float4*)&Ps[(tm * 4 + i) * AT_STRIDE + tn * 4] =
                make_float4(s[i][0], s[i][1], s[i][2], s[i][3]);
        }
        __syncthreads();

        // O += P V   (thread owns rows tm*4.. , d-cols tn*4..)
#pragma unroll 8
        for (int n = 0; n < 64; n++) {
            float4 vf = *(const float4*)&Vs[n * AT_STRIDE + tn * 4];
            float va[4] = {vf.x, vf.y, vf.z, vf.w};
            float p0 = Ps[(tm * 4 + 0) * AT_STRIDE + n];
            float p1 = Ps[(tm * 4 + 1) * AT_STRIDE + n];
            float p2 = Ps[(tm * 4 + 2) * AT_STRIDE + n];
            float p3 = Ps[(tm * 4 + 3) * AT_STRIDE + n];
            float pa[4] = {p0, p1, p2, p3};
#pragma unroll
            for (int i = 0; i < 4; i++)
#pragma unroll
                for (int j = 0; j < 4; j++)
                    o[i][j] = fmaf(pa[i], va[j], o[i][j]);
        }
    }

    // Normalize and store to [B,S,D] layout (head h occupies cols h*64..)
#pragma unroll
    for (int i = 0; i < 4; i++) {
        float inv_l = 1.0f / l_run[i];
        const size_t row = (size_t)(qt * 64 + tm * 4 + i);
        float4 v = make_float4(o[i][0] * inv_l, o[i][1] * inv_l,
                               o[i][2] * inv_l, o[i][3] * inv_l);
        *(float4*)(O + base + row * DD + tn * 4) = v;
    }
}

// ---------------------------------------------------------------------------
// Launch
// ---------------------------------------------------------------------------
extern "C" void kernel_launch(void* const* d_in, const int* in_sizes, int n_in,
                              void* d_out, int out_size)
{
    const float* xQ = (const float*)d_in[0];
    const float* xK = (const float*)d_in[1];
    const float* xV = (const float*)d_in[2];
    const float* Wq = (const float*)d_in[3];
    const float* bq = (const float*)d_in[4];
    const float* Wk = (const float*)d_in[5];
    const float* bk = (const float*)d_in[6];
    const float* Wv = (const float*)d_in[7];
    const float* bv = (const float*)d_in[8];
    const float* Wo = (const float*)d_in[9];
    const float* bo = (const float*)d_in[10];
    float* out = (float*)d_out;

    float *Qb, *Kb, *Vb, *AOb;
    cudaGetSymbolAddress((void**)&Qb,  g_Q);
    cudaGetSymbolAddress((void**)&Kb,  g_K);
    cudaGetSymbolAddress((void**)&Vb,  g_V);
    cudaGetSymbolAddress((void**)&AOb, g_AO);

    cudaFuncSetAttribute(attn_kernel,
                         cudaFuncAttributeMaxDynamicSharedMemorySize,
                         AT_SMEM_BYTES);

    dim3 gblk(256);
    dim3 ggrid(DD / 128, MTOT / 128);   // (8, 64)

    gemm_bias_kernel<<<ggrid, gblk>>>(xQ, Wq, bq, Qb, MTOT, DD, DD);
    gemm_bias_kernel<<<ggrid, gblk>>>(xK, Wk, bk, Kb, MTOT, DD, DD);
    gemm_bias_kernel<<<ggrid, gblk>>>(xV, Wv, bv, Vb, MTOT, DD, DD);

    dim3 agrid(SS / 64, HH, BB);        // (32, 16, 4)
    attn_kernel<<<agrid, gblk, AT_SMEM_BYTES>>>(Qb, Kb, Vb, AOb);

    gemm_bias_kernel<<<ggrid, gblk>>>(AOb, Wo, bo, out, MTOT, DD, DD);
}

// round 7
// speedup vs baseline: 2.4125x; 2.4125x over previous
#include <cuda_runtime.h>
#include <cuda_bf16.h>
#include <cstdint>

// Problem constants
#define BB   4
#define SS   2048
#define DD   1024
#define HH   16
#define DKK  64
#define MTOT (BB*SS)

// Scratch (no cudaMalloc allowed)
__device__ float g_Q [BB*SS*DD];
__device__ float g_K [BB*SS*DD];
__device__ float g_V [BB*SS*DD];
__device__ float g_AO[BB*SS*DD];

// ---------------------------------------------------------------------------
// Warp-MMA helpers (sm_80+ PTX: compiles for plain sm_103)
// ---------------------------------------------------------------------------
__device__ __forceinline__ uint32_t smem_u32(const void* p) {
    uint32_t a;
    asm("{ .reg .u64 t; cvta.to.shared.u64 t, %1; cvt.u32.u64 %0, t; }"
        : "=r"(a) : "l"(p));
    return a;
}

__device__ __forceinline__ void ldm_x4(uint32_t& r0, uint32_t& r1,
                                       uint32_t& r2, uint32_t& r3, uint32_t addr) {
    asm volatile("ldmatrix.sync.aligned.m8n8.x4.shared.b16 {%0,%1,%2,%3}, [%4];"
                 : "=r"(r0), "=r"(r1), "=r"(r2), "=r"(r3) : "r"(addr));
}

__device__ __forceinline__ void ldm_x4_t(uint32_t& r0, uint32_t& r1,
                                         uint32_t& r2, uint32_t& r3, uint32_t addr) {
    asm volatile("ldmatrix.sync.aligned.m8n8.x4.trans.shared.b16 {%0,%1,%2,%3}, [%4];"
                 : "=r"(r0), "=r"(r1), "=r"(r2), "=r"(r3) : "r"(addr));
}

__device__ __forceinline__ void mma16816(float* d,
                                         uint32_t a0, uint32_t a1, uint32_t a2, uint32_t a3,
                                         uint32_t b0, uint32_t b1) {
    asm volatile(
        "mma.sync.aligned.m16n8k16.row.col.f32.bf16.bf16.f32 "
        "{%0,%1,%2,%3}, {%4,%5,%6,%7}, {%8,%9}, {%0,%1,%2,%3};"
        : "+f"(d[0]), "+f"(d[1]), "+f"(d[2]), "+f"(d[3])
        : "r"(a0), "r"(a1), "r"(a2), "r"(a3), "r"(b0), "r"(b1));
}

// fp32 pair -> bf16x2 hi (round-to-nearest) + bf16x2 lo (residual)
__device__ __forceinline__ void split2(float x0, float x1, uint32_t& h, uint32_t& l) {
    asm("cvt.rn.bf16x2.f32 %0, %1, %2;" : "=r"(h) : "f"(x1), "f"(x0));
    float h0 = __uint_as_float(h << 16);
    float h1 = __uint_as_float(h & 0xffff0000u);
    asm("cvt.rn.bf16x2.f32 %0, %1, %2;" : "=r"(l) : "f"(x1 - h1), "f"(x0 - h0));
}

// ---------------------------------------------------------------------------
// GEMM: C[M=8192,N=1024] = A @ W^T + bias.  HMMA bf16-split, fp32 accum.
// CTA tile 128x128, BK=32.  8 warps = 4(m) x 2(n); warp tile 32x64.
// SMEM rows padded to 40 bf16 (80B) -> conflict-free ldmatrix.
// ---------------------------------------------------------------------------
#define GST 40   // bf16 per smem row

__global__ __launch_bounds__(256) void gemm_tc(
    const float* __restrict__ A, const float* __restrict__ W,
    const float* __restrict__ bias, float* __restrict__ C)
{
    __shared__ uint16_t Ahi[128 * GST], Alo[128 * GST];
    __shared__ uint16_t Bhi[128 * GST], Blo[128 * GST];

    const int tid  = threadIdx.x;
    const int lane = tid & 31;
    const int wid  = tid >> 5;
    const int wm   = wid & 3;          // m block of 32
    const int wn   = wid >> 2;         // n block of 64
    const int bm   = blockIdx.y * 128;
    const int bn   = blockIdx.x * 128;

    const uint32_t sAhi = smem_u32(Ahi), sAlo = smem_u32(Alo);
    const uint32_t sBhi = smem_u32(Bhi), sBlo = smem_u32(Blo);

    float acc[2][8][4];
#pragma unroll
    for (int mt = 0; mt < 2; mt++)
#pragma unroll
        for (int nt = 0; nt < 8; nt++)
#pragma unroll
            for (int q = 0; q < 4; q++) acc[mt][nt][q] = 0.f;

    // ldmatrix source offsets
    const int a_row = wm * 32 + (lane & 15);
    const int a_kh  = (lane >> 4) * 8;
    const int b_off = (lane & 7) + ((lane & 16) ? 8 : 0);
    const int b_kh  = (lane & 8) ? 8 : 0;

    for (int k0 = 0; k0 < DD; k0 += 32) {
        __syncthreads();
        // Load 128x32 fp32 of A and W, split to bf16 hi/lo in SMEM
#pragma unroll
        for (int it = 0; it < 4; it++) {
            int idx = tid + it * 256;          // 0..1023
            int r   = idx >> 3;                // 0..127
            int c4  = idx & 7;                 // float4 within 32 k
            uint32_t soff = (uint32_t)(r * GST + c4 * 4) * 2;  // bytes

            float4 av = *(const float4*)(A + (size_t)(bm + r) * DD + k0 + c4 * 4);
            uint32_t h0, l0, h1, l1;
            split2(av.x, av.y, h0, l0);
            split2(av.z, av.w, h1, l1);
            *(uint2*)((char*)Ahi + soff) = make_uint2(h0, h1);
            *(uint2*)((char*)Alo + soff) = make_uint2(l0, l1);

            float4 wv = *(const float4*)(W + (size_t)(bn + r) * DD + k0 + c4 * 4);
            split2(wv.x, wv.y, h0, l0);
            split2(wv.z, wv.w, h1, l1);
            *(uint2*)((char*)Bhi + soff) = make_uint2(h0, h1);
            *(uint2*)((char*)Blo + soff) = make_uint2(l0, l1);
        }
        __syncthreads();

#pragma unroll
        for (int ks = 0; ks < 2; ks++) {
            const int kb = ks * 16;
            uint32_t ah[2][4], al[2][4];
#pragma unroll
            for (int mt = 0; mt < 2; mt++) {
                uint32_t off = (uint32_t)((a_row + mt * 16) * GST + kb + a_kh) * 2;
                ldm_x4(ah[mt][0], ah[mt][1], ah[mt][2], ah[mt][3], sAhi + off);
                ldm_x4(al[mt][0], al[mt][1], al[mt][2], al[mt][3], sAlo + off);
            }
#pragma unroll
            for (int ng = 0; ng < 4; ng++) {
                uint32_t off = (uint32_t)((wn * 64 + ng * 16 + b_off) * GST + kb + b_kh) * 2;
                uint32_t bh0, bh1, bh2, bh3, bl0, bl1, bl2, bl3;
                ldm_x4(bh0, bh1, bh2, bh3, sBhi + off);
                ldm_x4(bl0, bl1, bl2, bl3, sBlo + off);
#pragma unroll
                for (int mt = 0; mt < 2; mt++) {
                    mma16816(acc[mt][2*ng],   ah[mt][0], ah[mt][1], ah[mt][2], ah[mt][3], bh0, bh1);
                    mma16816(acc[mt][2*ng],   ah[mt][0], ah[mt][1], ah[mt][2], ah[mt][3], bl0, bl1);
                    mma16816(acc[mt][2*ng],   al[mt][0], al[mt][1], al[mt][2], al[mt][3], bh0, bh1);
                    mma16816(acc[mt][2*ng+1], ah[mt][0], ah[mt][1], ah[mt][2], ah[mt][3], bh2, bh3);
                    mma16816(acc[mt][2*ng+1], ah[mt][0], ah[mt][1], ah[mt][2], ah[mt][3], bl2, bl3);
                    mma16816(acc[mt][2*ng+1], al[mt][0], al[mt][1], al[mt][2], al[mt][3], bh2, bh3);
                }
            }
        }
    }

    // Epilogue: C-frag (row lane/4 [+8], col 2*(lane%4))
#pragma unroll
    for (int mt = 0; mt < 2; mt++) {
#pragma unroll
        for (int nt = 0; nt < 8; nt++) {
            int row = bm + wm * 32 + mt * 16 + (lane >> 2);
            int col = bn + wn * 64 + nt * 8 + (lane & 3) * 2;
            float b0 = bias[col], b1 = bias[col + 1];
            *(float2*)(C + (size_t)row * DD + col) =
                make_float2(acc[mt][nt][0] + b0, acc[mt][nt][1] + b1);
            *(float2*)(C + (size_t)(row + 8) * DD + col) =
                make_float2(acc[mt][nt][2] + b0, acc[mt][nt][3] + b1);
        }
    }
}

// ---------------------------------------------------------------------------
// Flash attention on HMMA.
// CTA: 128 q-rows x one (b,h).  8 warps, 16 q-rows each.  KV tiles of 64.
// QK^T: bf16-split (3 products).  PV: bf16-split (3 products) -- the direct
// bf16 PV path measured rel_err 2.1e-3 (P and V rounding do NOT average down
// against the softmax-weighted output).
// SMEM rows padded to 72 bf16 (144B) -> conflict-free ldmatrix.
// ---------------------------------------------------------------------------
#define AST 72
#define AQH 0
#define AQL (128 * AST)
#define AKH (AQL + 128 * AST)
#define AKL (AKH + 64 * AST)
#define AVH (AKL + 64 * AST)
#define AVL (AVH + 64 * AST)
#define AT_SMEM ((AVL + 64 * AST) * 2)   // bytes = 73728

__global__ __launch_bounds__(256) void attn_tc(
    const float* __restrict__ Q, const float* __restrict__ K,
    const float* __restrict__ V, float* __restrict__ O)
{
    extern __shared__ uint16_t sm16[];
    const uint32_t sb = smem_u32(sm16);

    const int qt = blockIdx.x;   // 0..15 (128 rows each)
    const int h  = blockIdx.y;
    const int b  = blockIdx.z;

    const int tid  = threadIdx.x;
    const int lane = tid & 31;
    const int wid  = tid >> 5;
    const int m0   = wid * 16;

    const size_t base = ((size_t)b * SS) * DD + (size_t)h * DKK;

    // Load + scale + split Q tile 128x64
    {
        const float* Qp = Q + base + (size_t)(qt * 128) * DD;
#pragma unroll
        for (int it = 0; it < 8; it++) {
            int idx = tid + it * 256;          // 0..2047
            int r   = idx >> 4;                // 0..127
            int c4  = idx & 15;                // float4 in 64 d
            float4 v = *(const float4*)(Qp + (size_t)r * DD + c4 * 4);
            uint32_t h0, l0, h1, l1;
            split2(v.x * 0.125f, v.y * 0.125f, h0, l0);
            split2(v.z * 0.125f, v.w * 0.125f, h1, l1);
            uint32_t soff = (uint32_t)(r * AST + c4 * 4) * 2;
            *(uint2*)((char*)sm16 + AQH * 2 + soff) = make_uint2(h0, h1);
            *(uint2*)((char*)sm16 + AQL * 2 + soff) = make_uint2(l0, l1);
        }
    }

    float o[8][4];
#pragma unroll
    for (int nt = 0; nt < 8; nt++)
#pragma unroll
        for (int q = 0; q < 4; q++) o[nt][q] = 0.f;
    float m0r = -1e30f, m1r = -1e30f, l0r = 0.f, l1r = 0.f;

    const int a_row = m0 + (lane & 15);
    const int a_kh  = (lane >> 4) * 8;
    const int b_off = (lane & 7) + ((lane & 16) ? 8 : 0);
    const int b_kh  = (lane & 8) ? 8 : 0;
    const int v_row = (lane & 15);
    const int v_kh  = (lane & 16) ? 8 : 0;

    for (int kt = 0; kt < SS / 64; kt++) {
        __syncthreads();   // previous iteration's smem reads complete
        // Load K (split) and V (split) tiles: 64x64
        {
            const float* Kp = K + base + (size_t)(kt * 64) * DD;
            const float* Vp = V + base + (size_t)(kt * 64) * DD;
#pragma unroll
            for (int it = 0; it < 4; it++) {
                int idx = tid + it * 256;      // 0..1023
                int r   = idx >> 4;            // 0..63
                int c4  = idx & 15;
                uint32_t soff = (uint32_t)(r * AST + c4 * 4) * 2;

                float4 kv = *(const float4*)(Kp + (size_t)r * DD + c4 * 4);
                uint32_t h0, l0, h1, l1;
                split2(kv.x, kv.y, h0, l0);
                split2(kv.z, kv.w, h1, l1);
                *(uint2*)((char*)sm16 + AKH * 2 + soff) = make_uint2(h0, h1);
                *(uint2*)((char*)sm16 + AKL * 2 + soff) = make_uint2(l0, l1);

                float4 vv = *(const float4*)(Vp + (size_t)r * DD + c4 * 4);
                split2(vv.x, vv.y, h0, l0);
                split2(vv.z, vv.w, h1, l1);
                *(uint2*)((char*)sm16 + AVH * 2 + soff) = make_uint2(h0, h1);
                *(uint2*)((char*)sm16 + AVL * 2 + soff) = make_uint2(l0, l1);
            }
        }
        __syncthreads();

        // S = Q K^T  (128x64, warp does 16x64)
        float s[8][4];
#pragma unroll
        for (int nt = 0; nt < 8; nt++)
#pragma unroll
            for (int q = 0; q < 4; q++) s[nt][q] = 0.f;

#pragma unroll
        for (int ks = 0; ks < 4; ks++) {
            const int kb = ks * 16;
            uint32_t qh[4], ql[4];
            uint32_t qoff = (uint32_t)(a_row * AST + kb + a_kh) * 2;
            ldm_x4(qh[0], qh[1], qh[2], qh[3], sb + AQH * 2 + qoff);
            ldm_x4(ql[0], ql[1], ql[2], ql[3], sb + AQL * 2 + qoff);
#pragma unroll
            for (int ng = 0; ng < 4; ng++) {
                uint32_t koff = (uint32_t)((ng * 16 + b_off) * AST + kb + b_kh) * 2;
                uint32_t kh0, kh1, kh2, kh3, kl0, kl1, kl2, kl3;
                ldm_x4(kh0, kh1, kh2, kh3, sb + AKH * 2 + koff);
                ldm_x4(kl0, kl1, kl2, kl3, sb + AKL * 2 + koff);
                mma16816(s[2*ng],   qh[0], qh[1], qh[2], qh[3], kh0, kh1);
                mma16816(s[2*ng],   qh[0], qh[1], qh[2], qh[3], kl0, kl1);
                mma16816(s[2*ng],   ql[0], ql[1], ql[2], ql[3], kh0, kh1);
                mma16816(s[2*ng+1], qh[0], qh[1], qh[2], qh[3], kh2, kh3);
                mma16816(s[2*ng+1], qh[0], qh[1], qh[2], qh[3], kl2, kl3);
                mma16816(s[2*ng+1], ql[0], ql[1], ql[2], ql[3], kh2, kh3);
            }
        }

        // Online softmax in C-fragments. Thread owns rows (lane>>2) and +8.
        float mx0 = -1e30f, mx1 = -1e30f;
#pragma unroll
        for (int nt = 0; nt < 8; nt++) {
            mx0 = fmaxf(mx0, fmaxf(s[nt][0], s[nt][1]));
            mx1 = fmaxf(mx1, fmaxf(s[nt][2], s[nt][3]));
        }
#pragma unroll
        for (int off = 1; off <= 2; off <<= 1) {
            mx0 = fmaxf(mx0, __shfl_xor_sync(0xffffffffu, mx0, off));
            mx1 = fmaxf(mx1, __shfl_xor_sync(0xffffffffu, mx1, off));
        }
        float mn0 = fmaxf(m0r, mx0), mn1 = fmaxf(m1r, mx1);
        float al0 = __expf(m0r - mn0), al1 = __expf(m1r - mn1);
        m0r = mn0; m1r = mn1;

        float sum0 = 0.f, sum1 = 0.f;
#pragma unroll
        for (int nt = 0; nt < 8; nt++) {
            s[nt][0] = __expf(s[nt][0] - mn0);
            s[nt][1] = __expf(s[nt][1] - mn0);
            s[nt][2] = __expf(s[nt][2] - mn1);
            s[nt][3] = __expf(s[nt][3] - mn1);
            sum0 += s[nt][0] + s[nt][1];
            sum1 += s[nt][2] + s[nt][3];
        }
#pragma unroll
        for (int off = 1; off <= 2; off <<= 1) {
            sum0 += __shfl_xor_sync(0xffffffffu, sum0, off);
            sum1 += __shfl_xor_sync(0xffffffffu, sum1, off);
        }
        l0r = l0r * al0 + sum0;
        l1r = l1r * al1 + sum1;
#pragma unroll
        for (int nt = 0; nt < 8; nt++) {
            o[nt][0] *= al0; o[nt][1] *= al0;
            o[nt][2] *= al1; o[nt][3] *= al1;
        }

        // O += P V with P and V split (PhVh + PhVl + PlVh).
        // P: C-frag -> A-frag in-register; V via ldmatrix.trans.
#pragma unroll
        for (int ksj = 0; ksj < 4; ksj++) {
            uint32_t ph0, pl0, ph1, pl1, ph2, pl2, ph3, pl3;
            split2(s[2*ksj][0],   s[2*ksj][1],   ph0, pl0);
            split2(s[2*ksj][2],   s[2*ksj][3],   ph1, pl1);
            split2(s[2*ksj+1][0], s[2*ksj+1][1], ph2, pl2);
            split2(s[2*ksj+1][2], s[2*ksj+1][3], ph3, pl3);
#pragma unroll
            for (int ng = 0; ng < 4; ng++) {
                uint32_t voff = (uint32_t)((ksj * 16 + v_row) * AST + ng * 16 + v_kh) * 2;
                uint32_t vh0, vh1, vh2, vh3, vl0, vl1, vl2, vl3;
                ldm_x4_t(vh0, vh1, vh2, vh3, sb + AVH * 2 + voff);
                ldm_x4_t(vl0, vl1, vl2, vl3, sb + AVL * 2 + voff);
                mma16816(o[2*ng],   ph0, ph1, ph2, ph3, vh0, vh1);
                mma16816(o[2*ng],   ph0, ph1, ph2, ph3, vl0, vl1);
                mma16816(o[2*ng],   pl0, pl1, pl2, pl3, vh0, vh1);
                mma16816(o[2*ng+1], ph0, ph1, ph2, ph3, vh2, vh3);
                mma16816(o[2*ng+1], ph0, ph1, ph2, ph3, vl2, vl3);
                mma16816(o[2*ng+1], pl0, pl1, pl2, pl3, vh2, vh3);
            }
        }
    }

    // Normalize + store
    float inv0 = 1.f / l0r, inv1 = 1.f / l1r;
    const int row0 = qt * 128 + m0 + (lane >> 2);
#pragma unroll
    for (int nt = 0; nt < 8; nt++) {
        int col = nt * 8 + (lane & 3) * 2;
        *(float2*)(O + base + (size_t)row0 * DD + col) =
            make_float2(o[nt][0] * inv0, o[nt][1] * inv0);
        *(float2*)(O + base + (size_t)(row0 + 8) * DD + col) =
            make_float2(o[nt][2] * inv1, o[nt][3] * inv1);
    }
}

// ---------------------------------------------------------------------------
// Launch
// ---------------------------------------------------------------------------
extern "C" void kernel_launch(void* const* d_in, const int* in_sizes, int n_in,
                              void* d_out, int out_size)
{
    const float* xQ = (const float*)d_in[0];
    const float* xK = (const float*)d_in[1];
    const float* xV = (const float*)d_in[2];
    const float* Wq = (const float*)d_in[3];
    const float* bq = (const float*)d_in[4];
    const float* Wk = (const float*)d_in[5];
    const float* bk = (const float*)d_in[6];
    const float* Wv = (const float*)d_in[7];
    const float* bv = (const float*)d_in[8];
    const float* Wo = (const float*)d_in[9];
    const float* bo = (const float*)d_in[10];
    float* out = (float*)d_out;

    float *Qb, *Kb, *Vb, *AOb;
    cudaGetSymbolAddress((void**)&Qb,  g_Q);
    cudaGetSymbolAddress((void**)&Kb,  g_K);
    cudaGetSymbolAddress((void**)&Vb,  g_V);
    cudaGetSymbolAddress((void**)&AOb, g_AO);

    cudaFuncSetAttribute(attn_tc,
                         cudaFuncAttributeMaxDynamicSharedMemorySize, AT_SMEM);

    dim3 blk(256);
    dim3 ggrid(DD / 128, MTOT / 128);   // (8, 64)

    gemm_tc<<<ggrid, blk>>>(xQ, Wq, bq, Qb);
    gemm_tc<<<ggrid, blk>>>(xK, Wk, bk, Kb);
    gemm_tc<<<ggrid, blk>>>(xV, Wv, bv, Vb);

    dim3 agrid(SS / 128, HH, BB);       // (16, 16, 4)
    attn_tc<<<agrid, blk, AT_SMEM>>>(Qb, Kb, Vb, AOb);

    gemm_tc<<<ggrid, blk>>>(AOb, Wo, bo, out);
}

// round 8
// speedup vs baseline: 2.9514x; 1.2234x over previous
#include <cuda_runtime.h>
#include <cuda_bf16.h>
#include <cstdint>

// Problem constants
#define BB   4
#define SS   2048
#define DD   1024
#define HH   16
#define DKK  64
#define MTOT (BB*SS)
#define NELEM (MTOT*DD)      // 8388608
#define WELEM (DD*DD)        // 1048576

// Scratch (no cudaMalloc allowed) — all intermediates as bf16 hi/lo pairs
__device__ __nv_bfloat16 g_XH[NELEM], g_XL[NELEM];   // split of current x input
__device__ __nv_bfloat16 g_WH[WELEM], g_WL[WELEM];   // split of current W
__device__ __nv_bfloat16 g_QH[NELEM], g_QL[NELEM];
__device__ __nv_bfloat16 g_KH[NELEM], g_KL[NELEM];
__device__ __nv_bfloat16 g_VH[NELEM], g_VL[NELEM];
__device__ __nv_bfloat16 g_AH[NELEM], g_AL[NELEM];   // attention output

// ---------------------------------------------------------------------------
// Helpers
// ---------------------------------------------------------------------------
__device__ __forceinline__ uint32_t smem_u32(const void* p) {
    uint32_t a;
    asm("{ .reg .u64 t; cvta.to.shared.u64 t, %1; cvt.u32.u64 %0, t; }"
        : "=r"(a) : "l"(p));
    return a;
}

__device__ __forceinline__ void ldm_x4(uint32_t& r0, uint32_t& r1,
                                       uint32_t& r2, uint32_t& r3, uint32_t addr) {
    asm volatile("ldmatrix.sync.aligned.m8n8.x4.shared.b16 {%0,%1,%2,%3}, [%4];"
                 : "=r"(r0), "=r"(r1), "=r"(r2), "=r"(r3) : "r"(addr));
}

__device__ __forceinline__ void ldm_x4_t(uint32_t& r0, uint32_t& r1,
                                         uint32_t& r2, uint32_t& r3, uint32_t addr) {
    asm volatile("ldmatrix.sync.aligned.m8n8.x4.trans.shared.b16 {%0,%1,%2,%3}, [%4];"
                 : "=r"(r0), "=r"(r1), "=r"(r2), "=r"(r3) : "r"(addr));
}

__device__ __forceinline__ void mma16816(float* d,
                                         uint32_t a0, uint32_t a1, uint32_t a2, uint32_t a3,
                                         uint32_t b0, uint32_t b1) {
    asm volatile(
        "mma.sync.aligned.m16n8k16.row.col.f32.bf16.bf16.f32 "
        "{%0,%1,%2,%3}, {%4,%5,%6,%7}, {%8,%9}, {%0,%1,%2,%3};"
        : "+f"(d[0]), "+f"(d[1]), "+f"(d[2]), "+f"(d[3])
        : "r"(a0), "r"(a1), "r"(a2), "r"(a3), "r"(b0), "r"(b1));
}

__device__ __forceinline__ void split2(float x0, float x1, uint32_t& h, uint32_t& l) {
    asm("cvt.rn.bf16x2.f32 %0, %1, %2;" : "=r"(h) : "f"(x1), "f"(x0));
    float h0 = __uint_as_float(h << 16);
    float h1 = __uint_as_float(h & 0xffff0000u);
    asm("cvt.rn.bf16x2.f32 %0, %1, %2;" : "=r"(l) : "f"(x1 - h1), "f"(x0 - h0));
}

__device__ __forceinline__ void cp16(uint32_t s, const void* g) {
    asm volatile("cp.async.cg.shared.global [%0], [%1], 16;" :: "r"(s), "l"(g) : "memory");
}
#define CP_COMMIT() asm volatile("cp.async.commit_group;" ::: "memory")
#define CP_WAIT1()  asm volatile("cp.async.wait_group 1;" ::: "memory")
#define CP_WAIT0()  asm volatile("cp.async.wait_group 0;" ::: "memory")

// ---------------------------------------------------------------------------
// Elementwise fp32 -> bf16 hi/lo split
// ---------------------------------------------------------------------------
__global__ __launch_bounds__(256) void split_kernel(
    const float* __restrict__ x,
    __nv_bfloat16* __restrict__ hi, __nv_bfloat16* __restrict__ lo, int n4)
{
    int i = blockIdx.x * 256 + threadIdx.x;
    if (i >= n4) return;
    float4 v = ((const float4*)x)[i];
    uint32_t h0, l0, h1, l1;
    split2(v.x, v.y, h0, l0);
    split2(v.z, v.w, h1, l1);
    ((uint2*)hi)[i] = make_uint2(h0, h1);
    ((uint2*)lo)[i] = make_uint2(l0, l1);
}

// ---------------------------------------------------------------------------
// GEMM: C[8192,1024] = A @ W^T + bias, all operands pre-split bf16 hi/lo.
// CTA tile 128x128, BK=32, cp.async double-buffered.  8 warps = 4(m) x 2(n).
// mode 0: write fp32 C.  mode 1: write bf16 hi/lo with scale.
// ---------------------------------------------------------------------------
#define GST   40                    // bf16 per smem row (80B, 16B-aligned)
#define GARR  (128 * GST)           // elements per array
#define GSTAGE (4 * GARR)           // 4 arrays per stage
#define G_SMEM (2 * GSTAGE * 2)     // bytes = 81920

__global__ __launch_bounds__(256) void gemm_bf(
    const __nv_bfloat16* __restrict__ Ahi, const __nv_bfloat16* __restrict__ Alo,
    const __nv_bfloat16* __restrict__ Whi, const __nv_bfloat16* __restrict__ Wlo,
    const float* __restrict__ bias,
    float* __restrict__ Cf,
    __nv_bfloat16* __restrict__ Chi, __nv_bfloat16* __restrict__ Clo,
    int mode, float scale)
{
    extern __shared__ uint16_t gsm[];
    const uint32_t sb = smem_u32(gsm);

    const int tid  = threadIdx.x;
    const int lane = tid & 31;
    const int wid  = tid >> 5;
    const int wm   = wid & 3;
    const int wn   = wid >> 2;
    const int bm   = blockIdx.y * 128;
    const int bn   = blockIdx.x * 128;

    float acc[2][8][4];
#pragma unroll
    for (int mt = 0; mt < 2; mt++)
#pragma unroll
        for (int nt = 0; nt < 8; nt++)
#pragma unroll
            for (int q = 0; q < 4; q++) acc[mt][nt][q] = 0.f;

    const int a_row = wm * 32 + (lane & 15);
    const int a_kh  = (lane >> 4) * 8;
    const int b_off = (lane & 7) + ((lane & 16) ? 8 : 0);
    const int b_kh  = (lane & 8) ? 8 : 0;

    // cp.async load of one BK=32 chunk into stage s
    auto load_chunk = [&](int ch, int s) {
        const int k0 = ch * 32;
        const uint32_t sbase = sb + (uint32_t)s * GSTAGE * 2;
#pragma unroll
        for (int it = 0; it < 2; it++) {
            int idx = tid + it * 256;          // 0..511
            int r   = idx >> 2;                // 0..127
            int c   = idx & 3;                 // 16B chunk (8 bf16)
            uint32_t soff = (uint32_t)(r * GST + c * 8) * 2;
            size_t ga = (size_t)(bm + r) * DD + k0 + c * 8;
            size_t gb = (size_t)(bn + r) * DD + k0 + c * 8;
            cp16(sbase + 0 * GARR * 2 + soff, Ahi + ga);
            cp16(sbase + 1 * GARR * 2 + soff, Alo + ga);
            cp16(sbase + 2 * GARR * 2 + soff, Whi + gb);
            cp16(sbase + 3 * GARR * 2 + soff, Wlo + gb);
        }
    };

    load_chunk(0, 0);
    CP_COMMIT();

    for (int ch = 0; ch < 32; ch++) {
        if (ch < 31) {
            load_chunk(ch + 1, (ch + 1) & 1);
            CP_COMMIT();
            CP_WAIT1();
        } else {
            CP_WAIT0();
        }
        __syncthreads();

        const uint32_t sbase = sb + (uint32_t)(ch & 1) * GSTAGE * 2;
        const uint32_t sAhi = sbase;
        const uint32_t sAlo = sbase + 1 * GARR * 2;
        const uint32_t sBhi = sbase + 2 * GARR * 2;
        const uint32_t sBlo = sbase + 3 * GARR * 2;

#pragma unroll
        for (int ks = 0; ks < 2; ks++) {
            const int kb = ks * 16;
            uint32_t ah[2][4], al[2][4];
#pragma unroll
            for (int mt = 0; mt < 2; mt++) {
                uint32_t off = (uint32_t)((a_row + mt * 16) * GST + kb + a_kh) * 2;
                ldm_x4(ah[mt][0], ah[mt][1], ah[mt][2], ah[mt][3], sAhi + off);
                ldm_x4(al[mt][0], al[mt][1], al[mt][2], al[mt][3], sAlo + off);
            }
#pragma unroll
            for (int ng = 0; ng < 4; ng++) {
                uint32_t off = (uint32_t)((wn * 64 + ng * 16 + b_off) * GST + kb + b_kh) * 2;
                uint32_t bh0, bh1, bh2, bh3, bl0, bl1, bl2, bl3;
                ldm_x4(bh0, bh1, bh2, bh3, sBhi + off);
                ldm_x4(bl0, bl1, bl2, bl3, sBlo + off);
#pragma unroll
                for (int mt = 0; mt < 2; mt++) {
                    mma16816(acc[mt][2*ng],   ah[mt][0], ah[mt][1], ah[mt][2], ah[mt][3], bh0, bh1);
                    mma16816(acc[mt][2*ng],   ah[mt][0], ah[mt][1], ah[mt][2], ah[mt][3], bl0, bl1);
                    mma16816(acc[mt][2*ng],   al[mt][0], al[mt][1], al[mt][2], al[mt][3], bh0, bh1);
                    mma16816(acc[mt][2*ng+1], ah[mt][0], ah[mt][1], ah[mt][2], ah[mt][3], bh2, bh3);
                    mma16816(acc[mt][2*ng+1], ah[mt][0], ah[mt][1], ah[mt][2], ah[mt][3], bl2, bl3);
                    mma16816(acc[mt][2*ng+1], al[mt][0], al[mt][1], al[mt][2], al[mt][3], bh2, bh3);
                }
            }
        }
        __syncthreads();
    }

    // Epilogue
#pragma unroll
    for (int mt = 0; mt < 2; mt++) {
#pragma unroll
        for (int nt = 0; nt < 8; nt++) {
            int row = bm + wm * 32 + mt * 16 + (lane >> 2);
            int col = bn + wn * 64 + nt * 8 + (lane & 3) * 2;
            float b0 = bias[col], b1 = bias[col + 1];
            if (mode == 0) {
                *(float2*)(Cf + (size_t)row * DD + col) =
                    make_float2(acc[mt][nt][0] + b0, acc[mt][nt][1] + b1);
                *(float2*)(Cf + (size_t)(row + 8) * DD + col) =
                    make_float2(acc[mt][nt][2] + b0, acc[mt][nt][3] + b1);
            } else {
                uint32_t h, l;
                split2((acc[mt][nt][0] + b0) * scale, (acc[mt][nt][1] + b1) * scale, h, l);
                *(uint32_t*)(Chi + (size_t)row * DD + col) = h;
                *(uint32_t*)(Clo + (size_t)row * DD + col) = l;
                split2((acc[mt][nt][2] + b0) * scale, (acc[mt][nt][3] + b1) * scale, h, l);
                *(uint32_t*)(Chi + (size_t)(row + 8) * DD + col) = h;
                *(uint32_t*)(Clo + (size_t)(row + 8) * DD + col) = l;
            }
        }
    }
}

// ---------------------------------------------------------------------------
// Flash attention on HMMA, all inputs pre-split bf16 (Q pre-scaled by 1/8).
// CTA: 128 q-rows x one (b,h).  8 warps.  KV tiles of 64.
// Output written as bf16 hi/lo for the final GEMM.
// ---------------------------------------------------------------------------
#define AST 72
#define AQH 0
#define AQL (128 * AST)
#define AKH (AQL + 128 * AST)
#define AKL (AKH + 64 * AST)
#define AVH (AKL + 64 * AST)
#define AVL (AVH + 64 * AST)
#define AT_SMEM ((AVL + 64 * AST) * 2)   // 73728 bytes

__global__ __launch_bounds__(256) void attn_tc(
    const __nv_bfloat16* __restrict__ Qhi, const __nv_bfloat16* __restrict__ Qlo,
    const __nv_bfloat16* __restrict__ Khi, const __nv_bfloat16* __restrict__ Klo,
    const __nv_bfloat16* __restrict__ Vhi, const __nv_bfloat16* __restrict__ Vlo,
    __nv_bfloat16* __restrict__ Ohi, __nv_bfloat16* __restrict__ Olo)
{
    extern __shared__ uint16_t sm16[];
    const uint32_t sb = smem_u32(sm16);

    const int qt = blockIdx.x;
    const int h  = blockIdx.y;
    const int b  = blockIdx.z;

    const int tid  = threadIdx.x;
    const int lane = tid & 31;
    const int wid  = tid >> 5;
    const int m0   = wid * 16;

    const size_t base = ((size_t)b * SS) * DD + (size_t)h * DKK;

    // Load Q tile 128x64 (hi + lo), straight bf16 copies
    {
        const size_t qb = base + (size_t)(qt * 128) * DD;
#pragma unroll
        for (int it = 0; it < 4; it++) {
            int idx = tid + it * 256;          // 0..1023
            int r   = idx >> 3;                // 0..127
            int c   = idx & 7;                 // 16B chunk (8 bf16)
            size_t g = qb + (size_t)r * DD + c * 8;
            uint32_t soff = (uint32_t)(r * AST + c * 8) * 2;
            *(uint4*)((char*)sm16 + AQH * 2 + soff) = *(const uint4*)(Qhi + g);
            *(uint4*)((char*)sm16 + AQL * 2 + soff) = *(const uint4*)(Qlo + g);
        }
    }

    float o[8][4];
#pragma unroll
    for (int nt = 0; nt < 8; nt++)
#pragma unroll
        for (int q = 0; q < 4; q++) o[nt][q] = 0.f;
    float m0r = -1e30f, m1r = -1e30f, l0r = 0.f, l1r = 0.f;

    const int a_row = m0 + (lane & 15);
    const int a_kh  = (lane >> 4) * 8;
    const int b_off = (lane & 7) + ((lane & 16) ? 8 : 0);
    const int b_kh  = (lane & 8) ? 8 : 0;
    const int v_row = (lane & 15);
    const int v_kh  = (lane & 16) ? 8 : 0;

    for (int kt = 0; kt < SS / 64; kt++) {
        __syncthreads();
        // Load K/V tiles 64x64 (hi + lo each)
        {
            const size_t kb = base + (size_t)(kt * 64) * DD;
#pragma unroll
            for (int it = 0; it < 2; it++) {
                int idx = tid + it * 256;      // 0..511
                int r   = idx >> 3;            // 0..63
                int c   = idx & 7;
                size_t g = kb + (size_t)r * DD + c * 8;
                uint32_t soff = (uint32_t)(r * AST + c * 8) * 2;
                *(uint4*)((char*)sm16 + AKH * 2 + soff) = *(const uint4*)(Khi + g);
                *(uint4*)((char*)sm16 + AKL * 2 + soff) = *(const uint4*)(Klo + g);
                *(uint4*)((char*)sm16 + AVH * 2 + soff) = *(const uint4*)(Vhi + g);
                *(uint4*)((char*)sm16 + AVL * 2 + soff) = *(const uint4*)(Vlo + g);
            }
        }
        __syncthreads();

        // S = Q K^T
        float s[8][4];
#pragma unroll
        for (int nt = 0; nt < 8; nt++)
#pragma unroll
            for (int q = 0; q < 4; q++) s[nt][q] = 0.f;

#pragma unroll
        for (int ks = 0; ks < 4; ks++) {
            const int kb2 = ks * 16;
            uint32_t qh[4], ql[4];
            uint32_t qoff = (uint32_t)(a_row * AST + kb2 + a_kh) * 2;
            ldm_x4(qh[0], qh[1], qh[2], qh[3], sb + AQH * 2 + qoff);
            ldm_x4(ql[0], ql[1], ql[2], ql[3], sb + AQL * 2 + qoff);
#pragma unroll
            for (int ng = 0; ng < 4; ng++) {
                uint32_t koff = (uint32_t)((ng * 16 + b_off) * AST + kb2 + b_kh) * 2;
                uint32_t kh0, kh1, kh2, kh3, kl0, kl1, kl2, kl3;
                ldm_x4(kh0, kh1, kh2, kh3, sb + AKH * 2 + koff);
                ldm_x4(kl0, kl1, kl2, kl3, sb + AKL * 2 + koff);
                mma16816(s[2*ng],   qh[0], qh[1], qh[2], qh[3], kh0, kh1);
                mma16816(s[2*ng],   qh[0], qh[1], qh[2], qh[3], kl0, kl1);
                mma16816(s[2*ng],   ql[0], ql[1], ql[2], ql[3], kh0, kh1);
                mma16816(s[2*ng+1], qh[0], qh[1], qh[2], qh[3], kh2, kh3);
                mma16816(s[2*ng+1], qh[0], qh[1], qh[2], qh[3], kl2, kl3);
                mma16816(s[2*ng+1], ql[0], ql[1], ql[2], ql[3], kh2, kh3);
            }
        }

        // Online softmax in C-fragments
        float mx0 = -1e30f, mx1 = -1e30f;
#pragma unroll
        for (int nt = 0; nt < 8; nt++) {
            mx0 = fmaxf(mx0, fmaxf(s[nt][0], s[nt][1]));
            mx1 = fmaxf(mx1, fmaxf(s[nt][2], s[nt][3]));
        }
#pragma unroll
        for (int off = 1; off <= 2; off <<= 1) {
            mx0 = fmaxf(mx0, __shfl_xor_sync(0xffffffffu, mx0, off));
            mx1 = fmaxf(mx1, __shfl_xor_sync(0xffffffffu, mx1, off));
        }
        float mn0 = fmaxf(m0r, mx0), mn1 = fmaxf(m1r, mx1);
        float al0 = __expf(m0r - mn0), al1 = __expf(m1r - mn1);
        m0r = mn0; m1r = mn1;

        float sum0 = 0.f, sum1 = 0.f;
#pragma unroll
        for (int nt = 0; nt < 8; nt++) {
            s[nt][0] = __expf(s[nt][0] - mn0);
            s[nt][1] = __expf(s[nt][1] - mn0);
            s[nt][2] = __expf(s[nt][2] - mn1);
            s[nt][3] = __expf(s[nt][3] - mn1);
            sum0 += s[nt][0] + s[nt][1];
            sum1 += s[nt][2] + s[nt][3];
        }
#pragma unroll
        for (int off = 1; off <= 2; off <<= 1) {
            sum0 += __shfl_xor_sync(0xffffffffu, sum0, off);
            sum1 += __shfl_xor_sync(0xffffffffu, sum1, off);
        }
        l0r = l0r * al0 + sum0;
        l1r = l1r * al1 + sum1;
#pragma unroll
        for (int nt = 0; nt < 8; nt++) {
            o[nt][0] *= al0; o[nt][1] *= al0;
            o[nt][2] *= al1; o[nt][3] *= al1;
        }

        // O += P V with P and V split (PhVh + PhVl + PlVh)
#pragma unroll
        for (int ksj = 0; ksj < 4; ksj++) {
            uint32_t ph0, pl0, ph1, pl1, ph2, pl2, ph3, pl3;
            split2(s[2*ksj][0],   s[2*ksj][1],   ph0, pl0);
            split2(s[2*ksj][2],   s[2*ksj][3],   ph1, pl1);
            split2(s[2*ksj+1][0], s[2*ksj+1][1], ph2, pl2);
            split2(s[2*ksj+1][2], s[2*ksj+1][3], ph3, pl3);
#pragma unroll
            for (int ng = 0; ng < 4; ng++) {
                uint32_t voff = (uint32_t)((ksj * 16 + v_row) * AST + ng * 16 + v_kh) * 2;
                uint32_t vh0, vh1, vh2, vh3, vl0, vl1, vl2, vl3;
                ldm_x4_t(vh0, vh1, vh2, vh3, sb + AVH * 2 + voff);
                ldm_x4_t(vl0, vl1, vl2, vl3, sb + AVL * 2 + voff);
                mma16816(o[2*ng],   ph0, ph1, ph2, ph3, vh0, vh1);
                mma16816(o[2*ng],   ph0, ph1, ph2, ph3, vl0, vl1);
                mma16816(o[2*ng],   pl0, pl1, pl2, pl3, vh0, vh1);
                mma16816(o[2*ng+1], ph0, ph1, ph2, ph3, vh2, vh3);
                mma16816(o[2*ng+1], ph0, ph1, ph2, ph3, vl2, vl3);
                mma16816(o[2*ng+1], pl0, pl1, pl2, pl3, vh2, vh3);
            }
        }
    }

    // Normalize + store as bf16 hi/lo
    float inv0 = 1.f / l0r, inv1 = 1.f / l1r;
    const int row0 = qt * 128 + m0 + (lane >> 2);
#pragma unroll
    for (int nt = 0; nt < 8; nt++) {
        int col = nt * 8 + (lane & 3) * 2;
        uint32_t h, l;
        split2(o[nt][0] * inv0, o[nt][1] * inv0, h, l);
        *(uint32_t*)(Ohi + base + (size_t)row0 * DD + col) = h;
        *(uint32_t*)(Olo + base + (size_t)row0 * DD + col) = l;
        split2(o[nt][2] * inv1, o[nt][3] * inv1, h, l);
        *(uint32_t*)(Ohi + base + (size_t)(row0 + 8) * DD + col) = h;
        *(uint32_t*)(Olo + base + (size_t)(row0 + 8) * DD + col) = l;
    }
}

// ---------------------------------------------------------------------------
// Launch
// ---------------------------------------------------------------------------
extern "C" void kernel_launch(void* const* d_in, const int* in_sizes, int n_in,
                              void* d_out, int out_size)
{
    const float* xQ = (const float*)d_in[0];
    const float* xK = (const float*)d_in[1];
    const float* xV = (const float*)d_in[2];
    const float* Wq = (const float*)d_in[3];
    const float* bq = (const float*)d_in[4];
    const float* Wk = (const float*)d_in[5];
    const float* bk = (const float*)d_in[6];
    const float* Wv = (const float*)d_in[7];
    const float* bv = (const float*)d_in[8];
    const float* Wo = (const float*)d_in[9];
    const float* bo = (const float*)d_in[10];
    float* out = (float*)d_out;

    __nv_bfloat16 *XH, *XL, *WH, *WL, *QH, *QL, *KH, *KL, *VH, *VL, *AH, *AL;
    cudaGetSymbolAddress((void**)&XH, g_XH);  cudaGetSymbolAddress((void**)&XL, g_XL);
    cudaGetSymbolAddress((void**)&WH, g_WH);  cudaGetSymbolAddress((void**)&WL, g_WL);
    cudaGetSymbolAddress((void**)&QH, g_QH);  cudaGetSymbolAddress((void**)&QL, g_QL);
    cudaGetSymbolAddress((void**)&KH, g_KH);  cudaGetSymbolAddress((void**)&KL, g_KL);
    cudaGetSymbolAddress((void**)&VH, g_VH);  cudaGetSymbolAddress((void**)&VL, g_VL);
    cudaGetSymbolAddress((void**)&AH, g_AH);  cudaGetSymbolAddress((void**)&AL, g_AL);

    cudaFuncSetAttribute(gemm_bf,
                         cudaFuncAttributeMaxDynamicSharedMemorySize, G_SMEM);
    cudaFuncSetAttribute(attn_tc,
                         cudaFuncAttributeMaxDynamicSharedMemorySize, AT_SMEM);

    dim3 blk(256);
    dim3 ggrid(DD / 128, MTOT / 128);       // (8, 64)
    const int nX = NELEM / 4, nW = WELEM / 4;
    const int gX = (nX + 255) / 256, gW = (nW + 255) / 256;

    // Q = (xQ Wq^T + bq) * 1/8  -> bf16 hi/lo
    split_kernel<<<gX, blk>>>(xQ, XH, XL, nX);
    split_kernel<<<gW, blk>>>(Wq, WH, WL, nW);
    gemm_bf<<<ggrid, blk, G_SMEM>>>(XH, XL, WH, WL, bq,
                                    nullptr, QH, QL, 1, 0.125f);
    // K
    split_kernel<<<gX, blk>>>(xK, XH, XL, nX);
    split_kernel<<<gW, blk>>>(Wk, WH, WL, nW);
    gemm_bf<<<ggrid, blk, G_SMEM>>>(XH, XL, WH, WL, bk,
                                    nullptr, KH, KL, 1, 1.0f);
    // V
    split_kernel<<<gX, blk>>>(xV, XH, XL, nX);
    split_kernel<<<gW, blk>>>(Wv, WH, WL, nW);
    gemm_bf<<<ggrid, blk, G_SMEM>>>(XH, XL, WH, WL, bv,
                                    nullptr, VH, VL, 1, 1.0f);

    // Attention
    dim3 agrid(SS / 128, HH, BB);           // (16, 16, 4)
    attn_tc<<<agrid, blk, AT_SMEM>>>(QH, QL, KH, KL, VH, VL, AH, AL);

    // out = AO Wo^T + bo  (fp32)
    split_kernel<<<gW, blk>>>(Wo, WH, WL, nW);
    gemm_bf<<<ggrid, blk, G_SMEM>>>(AH, AL, WH, WL, bo,
                                    out, nullptr, nullptr, 0, 1.0f);
}

// round 10
// speedup vs baseline: 3.4665x; 1.1745x over previous
#include <cuda_runtime.h>
#include <cuda_bf16.h>
#include <cstdint>

// Problem constants
#define BB   4
#define SS   2048
#define DD   1024
#define HH   16
#define DKK  64
#define MTOT (BB*SS)
#define NELEM (MTOT*DD)      // 8388608
#define WELEM (DD*DD)        // 1048576

// Scratch (no cudaMalloc allowed) — all intermediates as bf16 hi/lo pairs
__device__ __nv_bfloat16 g_XQH[NELEM], g_XQL[NELEM];
__device__ __nv_bfloat16 g_XKH[NELEM], g_XKL[NELEM];
__device__ __nv_bfloat16 g_XVH[NELEM], g_XVL[NELEM];
__device__ __nv_bfloat16 g_WqH[WELEM], g_WqL[WELEM];
__device__ __nv_bfloat16 g_WkH[WELEM], g_WkL[WELEM];
__device__ __nv_bfloat16 g_WvH[WELEM], g_WvL[WELEM];
__device__ __nv_bfloat16 g_WoH[WELEM], g_WoL[WELEM];
__device__ __nv_bfloat16 g_QH[NELEM], g_QL[NELEM];
__device__ __nv_bfloat16 g_KH[NELEM], g_KL[NELEM];
__device__ __nv_bfloat16 g_VH[NELEM], g_VL[NELEM];
__device__ __nv_bfloat16 g_AH[NELEM], g_AL[NELEM];

// ---------------------------------------------------------------------------
// Helpers
// ---------------------------------------------------------------------------
__device__ __forceinline__ uint32_t smem_u32(const void* p) {
    uint32_t a;
    asm("{ .reg .u64 t; cvta.to.shared.u64 t, %1; cvt.u32.u64 %0, t; }"
        : "=r"(a) : "l"(p));
    return a;
}

__device__ __forceinline__ void ldm_x4(uint32_t& r0, uint32_t& r1,
                                       uint32_t& r2, uint32_t& r3, uint32_t addr) {
    asm volatile("ldmatrix.sync.aligned.m8n8.x4.shared.b16 {%0,%1,%2,%3}, [%4];"
                 : "=r"(r0), "=r"(r1), "=r"(r2), "=r"(r3) : "r"(addr));
}

__device__ __forceinline__ void ldm_x4_t(uint32_t& r0, uint32_t& r1,
                                         uint32_t& r2, uint32_t& r3, uint32_t addr) {
    asm volatile("ldmatrix.sync.aligned.m8n8.x4.trans.shared.b16 {%0,%1,%2,%3}, [%4];"
                 : "=r"(r0), "=r"(r1), "=r"(r2), "=r"(r3) : "r"(addr));
}

__device__ __forceinline__ void mma16816(float* d,
                                         uint32_t a0, uint32_t a1, uint32_t a2, uint32_t a3,
                                         uint32_t b0, uint32_t b1) {
    asm volatile(
        "mma.sync.aligned.m16n8k16.row.col.f32.bf16.bf16.f32 "
        "{%0,%1,%2,%3}, {%4,%5,%6,%7}, {%8,%9}, {%0,%1,%2,%3};"
        : "+f"(d[0]), "+f"(d[1]), "+f"(d[2]), "+f"(d[3])
        : "r"(a0), "r"(a1), "r"(a2), "r"(a3), "r"(b0), "r"(b1));
}

__device__ __forceinline__ void split2(float x0, float x1, uint32_t& h, uint32_t& l) {
    asm("cvt.rn.bf16x2.f32 %0, %1, %2;" : "=r"(h) : "f"(x1), "f"(x0));
    float h0 = __uint_as_float(h << 16);
    float h1 = __uint_as_float(h & 0xffff0000u);
    asm("cvt.rn.bf16x2.f32 %0, %1, %2;" : "=r"(l) : "f"(x1 - h1), "f"(x0 - h0));
}

__device__ __forceinline__ void cp16(uint32_t s, const void* g) {
    asm volatile("cp.async.cg.shared.global [%0], [%1], 16;" :: "r"(s), "l"(g) : "memory");
}
#define CP_COMMIT() asm volatile("cp.async.commit_group;" ::: "memory")
#define CP_WAIT1()  asm volatile("cp.async.wait_group 1;" ::: "memory")
#define CP_WAIT0()  asm volatile("cp.async.wait_group 0;" ::: "memory")

// ---------------------------------------------------------------------------
// Batched elementwise fp32 -> bf16 hi/lo split: 7 tensors in one launch
// ---------------------------------------------------------------------------
struct SplitBatch {
    const float* src[7];
    __nv_bfloat16* hi[7];
    __nv_bfloat16* lo[7];
    int n4[7];
};

__global__ __launch_bounds__(256) void split_all(SplitBatch sp) {
    const int z = blockIdx.y;
    const int i = blockIdx.x * 256 + threadIdx.x;
    if (i >= sp.n4[z]) return;
    float4 v = ((const float4*)sp.src[z])[i];
    uint32_t h0, l0, h1, l1;
    split2(v.x, v.y, h0, l0);
    split2(v.z, v.w, h1, l1);
    ((uint2*)sp.hi[z])[i] = make_uint2(h0, h1);
    ((uint2*)sp.lo[z])[i] = make_uint2(l0, l1);
}

// ---------------------------------------------------------------------------
// GEMM core: C[8192,1024] = A @ W^T + bias, pre-split bf16 hi/lo operands.
// CTA tile 128x128, BK=32, cp.async double-buffered.  8 warps = 4(m) x 2(n).
// ---------------------------------------------------------------------------
#define GST   40
#define GARR  (128 * GST)
#define GSTAGE (4 * GARR)
#define G_SMEM (2 * GSTAGE * 2)     // 81920 bytes

struct GemmBatch {
    const __nv_bfloat16 *Ah[3], *Al[3], *Wh[3], *Wl[3];
    const float* bias[3];
    __nv_bfloat16 *Ch[3], *Cl[3];
    float scale[3];
};

// Shared mainloop; writes acc. Returns nothing; caller does epilogue.
template <typename EPI>
__device__ __forceinline__ void gemm_body(
    const __nv_bfloat16* __restrict__ Ahi, const __nv_bfloat16* __restrict__ Alo,
    const __nv_bfloat16* __restrict__ Whi, const __nv_bfloat16* __restrict__ Wlo,
    EPI epi)
{
    extern __shared__ uint16_t gsm[];
    const uint32_t sb = smem_u32(gsm);

    const int tid  = threadIdx.x;
    const int lane = tid & 31;
    const int wid  = tid >> 5;
    const int wm   = wid & 3;
    const int wn   = wid >> 2;
    const int bm   = blockIdx.y * 128;
    const int bn   = blockIdx.x * 128;

    float acc[2][8][4];
#pragma unroll
    for (int mt = 0; mt < 2; mt++)
#pragma unroll
        for (int nt = 0; nt < 8; nt++)
#pragma unroll
            for (int q = 0; q < 4; q++) acc[mt][nt][q] = 0.f;

    const int a_row = wm * 32 + (lane & 15);
    const int a_kh  = (lane >> 4) * 8;
    const int b_off = (lane & 7) + ((lane & 16) ? 8 : 0);
    const int b_kh  = (lane & 8) ? 8 : 0;

    auto load_chunk = [&](int ch, int s) {
        const int k0 = ch * 32;
        const uint32_t sbase = sb + (uint32_t)s * GSTAGE * 2;
#pragma unroll
        for (int it = 0; it < 2; it++) {
            int idx = tid + it * 256;
            int r   = idx >> 2;
            int c   = idx & 3;
            uint32_t soff = (uint32_t)(r * GST + c * 8) * 2;
            size_t ga = (size_t)(bm + r) * DD + k0 + c * 8;
            size_t gb = (size_t)(bn + r) * DD + k0 + c * 8;
            cp16(sbase + 0 * GARR * 2 + soff, Ahi + ga);
            cp16(sbase + 1 * GARR * 2 + soff, Alo + ga);
            cp16(sbase + 2 * GARR * 2 + soff, Whi + gb);
            cp16(sbase + 3 * GARR * 2 + soff, Wlo + gb);
        }
    };

    load_chunk(0, 0);
    CP_COMMIT();

    for (int ch = 0; ch < 32; ch++) {
        if (ch < 31) {
            load_chunk(ch + 1, (ch + 1) & 1);
            CP_COMMIT();
            CP_WAIT1();
        } else {
            CP_WAIT0();
        }
        __syncthreads();

        const uint32_t sbase = sb + (uint32_t)(ch & 1) * GSTAGE * 2;
        const uint32_t sAhi = sbase;
        const uint32_t sAlo = sbase + 1 * GARR * 2;
        const uint32_t sBhi = sbase + 2 * GARR * 2;
        const uint32_t sBlo = sbase + 3 * GARR * 2;

#pragma unroll
        for (int ks = 0; ks < 2; ks++) {
            const int kb = ks * 16;
            uint32_t ah[2][4], al[2][4];
#pragma unroll
            for (int mt = 0; mt < 2; mt++) {
                uint32_t off = (uint32_t)((a_row + mt * 16) * GST + kb + a_kh) * 2;
                ldm_x4(ah[mt][0], ah[mt][1], ah[mt][2], ah[mt][3], sAhi + off);
                ldm_x4(al[mt][0], al[mt][1], al[mt][2], al[mt][3], sAlo + off);
            }
#pragma unroll
            for (int ng = 0; ng < 4; ng++) {
                uint32_t off = (uint32_t)((wn * 64 + ng * 16 + b_off) * GST + kb + b_kh) * 2;
                uint32_t bh0, bh1, bh2, bh3, bl0, bl1, bl2, bl3;
                ldm_x4(bh0, bh1, bh2, bh3, sBhi + off);
                ldm_x4(bl0, bl1, bl2, bl3, sBlo + off);
#pragma unroll
                for (int mt = 0; mt < 2; mt++) {
                    mma16816(acc[mt][2*ng],   ah[mt][0], ah[mt][1], ah[mt][2], ah[mt][3], bh0, bh1);
                    mma16816(acc[mt][2*ng],   ah[mt][0], ah[mt][1], ah[mt][2], ah[mt][3], bl0, bl1);
                    mma16816(acc[mt][2*ng],   al[mt][0], al[mt][1], al[mt][2], al[mt][3], bh0, bh1);
                    mma16816(acc[mt][2*ng+1], ah[mt][0], ah[mt][1], ah[mt][2], ah[mt][3], bh2, bh3);
                    mma16816(acc[mt][2*ng+1], ah[mt][0], ah[mt][1], ah[mt][2], ah[mt][3], bl2, bl3);
                    mma16816(acc[mt][2*ng+1], al[mt][0], al[mt][1], al[mt][2], al[mt][3], bh2, bh3);
                }
            }
        }
        __syncthreads();
    }

#pragma unroll
    for (int mt = 0; mt < 2; mt++) {
#pragma unroll
        for (int nt = 0; nt < 8; nt++) {
            int row = bm + wm * 32 + mt * 16 + (lane >> 2);
            int col = bn + wn * 64 + nt * 8 + (lane & 3) * 2;
            epi(row, col, acc[mt][nt]);
        }
    }
}

// Projections: 3 GEMMs in one launch (z selects), bf16 hi/lo output.
__global__ __launch_bounds__(256) void gemm_proj(GemmBatch gb) {
    const int z = blockIdx.z;
    const __nv_bfloat16* Ahi = gb.Ah[z];
    const __nv_bfloat16* Alo = gb.Al[z];
    const __nv_bfloat16* Whi = gb.Wh[z];
    const __nv_bfloat16* Wlo = gb.Wl[z];
    const float* bias = gb.bias[z];
    __nv_bfloat16* Chi = gb.Ch[z];
    __nv_bfloat16* Clo = gb.Cl[z];
    const float scale = gb.scale[z];

    gemm_body(Ahi, Alo, Whi, Wlo,
        [&](int row, int col, const float* a) {
            float b0 = bias[col], b1 = bias[col + 1];
            uint32_t h, l;
            split2((a[0] + b0) * scale, (a[1] + b1) * scale, h, l);
            *(uint32_t*)(Chi + (size_t)row * DD + col) = h;
            *(uint32_t*)(Clo + (size_t)row * DD + col) = l;
            split2((a[2] + b0) * scale, (a[3] + b1) * scale, h, l);
            *(uint32_t*)(Chi + (size_t)(row + 8) * DD + col) = h;
            *(uint32_t*)(Clo + (size_t)(row + 8) * DD + col) = l;
        });
}

// Final GEMM: fp32 output.
__global__ __launch_bounds__(256) void gemm_out(
    const __nv_bfloat16* __restrict__ Ahi, const __nv_bfloat16* __restrict__ Alo,
    const __nv_bfloat16* __restrict__ Whi, const __nv_bfloat16* __restrict__ Wlo,
    const float* __restrict__ bias, float* __restrict__ Cf)
{
    gemm_body(Ahi, Alo, Whi, Wlo,
        [&](int row, int col, const float* a) {
            float b0 = bias[col], b1 = bias[col + 1];
            *(float2*)(Cf + (size_t)row * DD + col) = make_float2(a[0] + b0, a[1] + b1);
            *(float2*)(Cf + (size_t)(row + 8) * DD + col) = make_float2(a[2] + b0, a[3] + b1);
        });
}

// ---------------------------------------------------------------------------
// Flash attention on HMMA, pre-split bf16 inputs (Q pre-scaled by 1/8).
// CTA: 128 q-rows x one (b,h).  8 warps.  KV tiles of 64, cp.async 2-stage.
// ---------------------------------------------------------------------------
#define AST  72
#define AQH  0
#define AQL  (128 * AST)
#define AKV0 (2 * 128 * AST)          // 18432 elems
#define TKV  (64 * AST)               // 4608 elems per array
#define SKV  (4 * TKV)                // stage: KH,KL,VH,VL
#define AT_SMEM ((AKV0 + 2 * SKV) * 2)  // 110592 bytes

__global__ __launch_bounds__(256, 2) void attn_tc(
    const __nv_bfloat16* __restrict__ Qhi, const __nv_bfloat16* __restrict__ Qlo,
    const __nv_bfloat16* __restrict__ Khi, const __nv_bfloat16* __restrict__ Klo,
    const __nv_bfloat16* __restrict__ Vhi, const __nv_bfloat16* __restrict__ Vlo,
    __nv_bfloat16* __restrict__ Ohi, __nv_bfloat16* __restrict__ Olo)
{
    extern __shared__ uint16_t sm16[];
    const uint32_t sb = smem_u32(sm16);

    const int qt = blockIdx.x;
    const int h  = blockIdx.y;
    const int b  = blockIdx.z;

    const int tid  = threadIdx.x;
    const int lane = tid & 31;
    const int wid  = tid >> 5;
    const int m0   = wid * 16;

    const size_t base = ((size_t)b * SS) * DD + (size_t)h * DKK;

    // Load Q tile 128x64 (hi + lo)
    {
        const size_t qb = base + (size_t)(qt * 128) * DD;
#pragma unroll
        for (int it = 0; it < 4; it++) {
            int idx = tid + it * 256;
            int r   = idx >> 3;
            int c   = idx & 7;
            size_t g = qb + (size_t)r * DD + c * 8;
            uint32_t soff = (uint32_t)(r * AST + c * 8) * 2;
            *(uint4*)((char*)sm16 + AQH * 2 + soff) = *(const uint4*)(Qhi + g);
            *(uint4*)((char*)sm16 + AQL * 2 + soff) = *(const uint4*)(Qlo + g);
        }
    }

    auto load_kv = [&](int kt, int s) {
        const size_t kb = base + (size_t)(kt * 64) * DD;
        const uint32_t sbase = sb + (uint32_t)(AKV0 + s * SKV) * 2;
#pragma unroll
        for (int it = 0; it < 2; it++) {
            int idx = tid + it * 256;
            int r   = idx >> 3;
            int c   = idx & 7;
            size_t g = kb + (size_t)r * DD + c * 8;
            uint32_t soff = (uint32_t)(r * AST + c * 8) * 2;
            cp16(sbase + 0 * TKV * 2 + soff, Khi + g);
            cp16(sbase + 1 * TKV * 2 + soff, Klo + g);
            cp16(sbase + 2 * TKV * 2 + soff, Vhi + g);
            cp16(sbase + 3 * TKV * 2 + soff, Vlo + g);
        }
    };

    float o[8][4];
#pragma unroll
    for (int nt = 0; nt < 8; nt++)
#pragma unroll
        for (int q = 0; q < 4; q++) o[nt][q] = 0.f;
    float m0r = -1e30f, m1r = -1e30f, l0r = 0.f, l1r = 0.f;

    const int a_row = m0 + (lane & 15);
    const int a_kh  = (lane >> 4) * 8;
    const int b_off = (lane & 7) + ((lane & 16) ? 8 : 0);
    const int b_kh  = (lane & 8) ? 8 : 0;
    const int v_row = (lane & 15);
    const int v_kh  = (lane & 16) ? 8 : 0;

    load_kv(0, 0);
    CP_COMMIT();

    for (int kt = 0; kt < SS / 64; kt++) {
        if (kt < SS / 64 - 1) {
            load_kv(kt + 1, (kt + 1) & 1);
            CP_COMMIT();
            CP_WAIT1();
        } else {
            CP_WAIT0();
        }
        __syncthreads();

        const uint32_t skv = sb + (uint32_t)(AKV0 + (kt & 1) * SKV) * 2;
        const uint32_t sKH = skv;
        const uint32_t sKL = skv + 1 * TKV * 2;
        const uint32_t sVH = skv + 2 * TKV * 2;
        const uint32_t sVL = skv + 3 * TKV * 2;

        // S = Q K^T
        float s[8][4];
#pragma unroll
        for (int nt = 0; nt < 8; nt++)
#pragma unroll
            for (int q = 0; q < 4; q++) s[nt][q] = 0.f;

#pragma unroll
        for (int ks = 0; ks < 4; ks++) {
            const int kb2 = ks * 16;
            uint32_t qh[4], ql[4];
            uint32_t qoff = (uint32_t)(a_row * AST + kb2 + a_kh) * 2;
            ldm_x4(qh[0], qh[1], qh[2], qh[3], sb + AQH * 2 + qoff);
            ldm_x4(ql[0], ql[1], ql[2], ql[3], sb + AQL * 2 + qoff);
#pragma unroll
            for (int ng = 0; ng < 4; ng++) {
                uint32_t koff = (uint32_t)((ng * 16 + b_off) * AST + kb2 + b_kh) * 2;
                uint32_t kh0, kh1, kh2, kh3, kl0, kl1, kl2, kl3;
                ldm_x4(kh0, kh1, kh2, kh3, sKH + koff);
                ldm_x4(kl0, kl1, kl2, kl3, sKL + koff);
                mma16816(s[2*ng],   qh[0], qh[1], qh[2], qh[3], kh0, kh1);
                mma16816(s[2*ng],   qh[0], qh[1], qh[2], qh[3], kl0, kl1);
                mma16816(s[2*ng],   ql[0], ql[1], ql[2], ql[3], kh0, kh1);
                mma16816(s[2*ng+1], qh[0], qh[1], qh[2], qh[3], kh2, kh3);
                mma16816(s[2*ng+1], qh[0], qh[1], qh[2], qh[3], kl2, kl3);
                mma16816(s[2*ng+1], ql[0], ql[1], ql[2], ql[3], kh2, kh3);
            }
        }

        // Online softmax in C-fragments
        float mx0 = -1e30f, mx1 = -1e30f;
#pragma unroll
        for (int nt = 0; nt < 8; nt++) {
            mx0 = fmaxf(mx0, fmaxf(s[nt][0], s[nt][1]));
            mx1 = fmaxf(mx1, fmaxf(s[nt][2], s[nt][3]));
        }
#pragma unroll
        for (int off = 1; off <= 2; off <<= 1) {
            mx0 = fmaxf(mx0, __shfl_xor_sync(0xffffffffu, mx0, off));
            mx1 = fmaxf(mx1, __shfl_xor_sync(0xffffffffu, mx1, off));
        }
        float mn0 = fmaxf(m0r, mx0), mn1 = fmaxf(m1r, mx1);
        float al0 = __expf(m0r - mn0), al1 = __expf(m1r - mn1);
        m0r = mn0; m1r = mn1;

        float sum0 = 0.f, sum1 = 0.f;
#pragma unroll
        for (int nt = 0; nt < 8; nt++) {
            s[nt][0] = __expf(s[nt][0] - mn0);
            s[nt][1] = __expf(s[nt][1] - mn0);
            s[nt][2] = __expf(s[nt][2] - mn1);
            s[nt][3] = __expf(s[nt][3] - mn1);
            sum0 += s[nt][0] + s[nt][1];
            sum1 += s[nt][2] + s[nt][3];
        }
#pragma unroll
        for (int off = 1; off <= 2; off <<= 1) {
            sum0 += __shfl_xor_sync(0xffffffffu, sum0, off);
            sum1 += __shfl_xor_sync(0xffffffffu, sum1, off);
        }
        l0r = l0r * al0 + sum0;
        l1r = l1r * al1 + sum1;
#pragma unroll
        for (int nt = 0; nt < 8; nt++) {
            o[nt][0] *= al0; o[nt][1] *= al0;
            o[nt][2] *= al1; o[nt][3] *= al1;
        }

        // O += P V with P and V split (PhVh + PhVl + PlVh)
#pragma unroll
        for (int ksj = 0; ksj < 4; ksj++) {
            uint32_t ph0, pl0, ph1, pl1, ph2, pl2, ph3, pl3;
            split2(s[2*ksj][0],   s[2*ksj][1],   ph0, pl0);
            split2(s[2*ksj][2],   s[2*ksj][3],   ph1, pl1);
            split2(s[2*ksj+1][0], s[2*ksj+1][1], ph2, pl2);
            split2(s[2*ksj+1][2], s[2*ksj+1][3], ph3, pl3);
#pragma unroll
            for (int ng = 0; ng < 4; ng++) {
                uint32_t voff = (uint32_t)((ksj * 16 + v_row) * AST + ng * 16 + v_kh) * 2;
                uint32_t vh0, vh1, vh2, vh3, vl0, vl1, vl2, vl3;
                ldm_x4_t(vh0, vh1, vh2, vh3, sVH + voff);
                ldm_x4_t(vl0, vl1, vl2, vl3, sVL + voff);
                mma16816(o[2*ng],   ph0, ph1, ph2, ph3, vh0, vh1);
                mma16816(o[2*ng],   ph0, ph1, ph2, ph3, vl0, vl1);
                mma16816(o[2*ng],   pl0, pl1, pl2, pl3, vh0, vh1);
                mma16816(o[2*ng+1], ph0, ph1, ph2, ph3, vh2, vh3);
                mma16816(o[2*ng+1], ph0, ph1, ph2, ph3, vl2, vl3);
                mma16816(o[2*ng+1], pl0, pl1, pl2, pl3, vh2, vh3);
            }
        }
        __syncthreads();
    }

    // Normalize + store as bf16 hi/lo
    float inv0 = 1.f / l0r, inv1 = 1.f / l1r;
    const int row0 = qt * 128 + m0 + (lane >> 2);
#pragma unroll
    for (int nt = 0; nt < 8; nt++) {
        int col = nt * 8 + (lane & 3) * 2;
        uint32_t h2, l2;
        split2(o[nt][0] * inv0, o[nt][1] * inv0, h2, l2);
        *(uint32_t*)(Ohi + base + (size_t)row0 * DD + col) = h2;
        *(uint32_t*)(Olo + base + (size_t)row0 * DD + col) = l2;
        split2(o[nt][2] * inv1, o[nt][3] * inv1, h2, l2);
        *(uint32_t*)(Ohi + base + (size_t)(row0 + 8) * DD + col) = h2;
        *(uint32_t*)(Olo + base + (size_t)(row0 + 8) * DD + col) = l2;
    }
}

// ---------------------------------------------------------------------------
// Launch
// ---------------------------------------------------------------------------
extern "C" void kernel_launch(void* const* d_in, const int* in_sizes, int n_in,
                              void* d_out, int out_size)
{
    const float* xQ = (const float*)d_in[0];
    const float* xK = (const float*)d_in[1];
    const float* xV = (const float*)d_in[2];
    const float* Wq = (const float*)d_in[3];
    const float* bq = (const float*)d_in[4];
    const float* Wk = (const float*)d_in[5];
    const float* bk = (const float*)d_in[6];
    const float* Wv = (const float*)d_in[7];
    const float* bv = (const float*)d_in[8];
    const float* Wo = (const float*)d_in[9];
    const float* bo = (const float*)d_in[10];
    float* out = (float*)d_out;

    __nv_bfloat16 *XQH,*XQL,*XKH,*XKL,*XVH,*XVL;
    __nv_bfloat16 *WqH,*WqL,*WkH,*WkL,*WvH,*WvL,*WoH,*WoL;
    __nv_bfloat16 *QH,*QL,*KH,*KL,*VH,*VL,*AH,*AL;
    cudaGetSymbolAddress((void**)&XQH, g_XQH); cudaGetSymbolAddress((void**)&XQL, g_XQL);
    cudaGetSymbolAddress((void**)&XKH, g_XKH); cudaGetSymbolAddress((void**)&XKL, g_XKL);
    cudaGetSymbolAddress((void**)&XVH, g_XVH); cudaGetSymbolAddress((void**)&XVL, g_XVL);
    cudaGetSymbolAddress((void**)&WqH, g_WqH); cudaGetSymbolAddress((void**)&WqL, g_WqL);
    cudaGetSymbolAddress((void**)&WkH, g_WkH); cudaGetSymbolAddress((void**)&WkL, g_WkL);
    cudaGetSymbolAddress((void**)&WvH, g_WvH); cudaGetSymbolAddress((void**)&WvL, g_WvL);
    cudaGetSymbolAddress((void**)&WoH, g_WoH); cudaGetSymbolAddress((void**)&WoL, g_WoL);
    cudaGetSymbolAddress((void**)&QH,  g_QH);  cudaGetSymbolAddress((void**)&QL,  g_QL);
    cudaGetSymbolAddress((void**)&KH,  g_KH);  cudaGetSymbolAddress((void**)&KL,  g_KL);
    cudaGetSymbolAddress((void**)&VH,  g_VH);  cudaGetSymbolAddress((void**)&VL,  g_VL);
    cudaGetSymbolAddress((void**)&AH,  g_AH);  cudaGetSymbolAddress((void**)&AL,  g_AL);

    cudaFuncSetAttribute(gemm_proj,
                         cudaFuncAttributeMaxDynamicSharedMemorySize, G_SMEM);
    cudaFuncSetAttribute(gemm_out,
                         cudaFuncAttributeMaxDynamicSharedMemorySize, G_SMEM);
    cudaFuncSetAttribute(attn_tc,
                         cudaFuncAttributeMaxDynamicSharedMemorySize, AT_SMEM);

    dim3 blk(256);
    const int nX = NELEM / 4, nW = WELEM / 4;

    // All 7 splits in one launch
    SplitBatch sp;
    sp.src[0]=xQ; sp.hi[0]=XQH; sp.lo[0]=XQL; sp.n4[0]=nX;
    sp.src[1]=xK; sp.hi[1]=XKH; sp.lo[1]=XKL; sp.n4[1]=nX;
    sp.src[2]=xV; sp.hi[2]=XVH; sp.lo[2]=XVL; sp.n4[2]=nX;
    sp.src[3]=Wq; sp.hi[3]=WqH; sp.lo[3]=WqL; sp.n4[3]=nW;
    sp.src[4]=Wk; sp.hi[4]=WkH; sp.lo[4]=WkL; sp.n4[4]=nW;
    sp.src[5]=Wv; sp.hi[5]=WvH; sp.lo[5]=WvL; sp.n4[5]=nW;
    sp.src[6]=Wo; sp.hi[6]=WoH; sp.lo[6]=WoL; sp.n4[6]=nW;
    split_all<<<dim3((nX + 255) / 256, 7), blk>>>(sp);

    // 3 projection GEMMs in one launch
    GemmBatch gb;
    gb.Ah[0]=XQH; gb.Al[0]=XQL; gb.Wh[0]=WqH; gb.Wl[0]=WqL; gb.bias[0]=bq;
    gb.Ch[0]=QH;  gb.Cl[0]=QL;  gb.scale[0]=0.125f;
    gb.Ah[1]=XKH; gb.Al[1]=XKL; gb.Wh[1]=WkH; gb.Wl[1]=WkL; gb.bias[1]=bk;
    gb.Ch[1]=KH;  gb.Cl[1]=KL;  gb.scale[1]=1.0f;
    gb.Ah[2]=XVH; gb.Al[2]=XVL; gb.Wh[2]=WvH; gb.Wl[2]=WvL; gb.bias[2]=bv;
    gb.Ch[2]=VH;  gb.Cl[2]=VL;  gb.scale[2]=1.0f;
    gemm_proj<<<dim3(DD / 128, MTOT / 128, 3), blk, G_SMEM>>>(gb);

    // Attention
    dim3 agrid(SS / 128, HH, BB);           // (16, 16, 4)
    attn_tc<<<agrid, blk, AT_SMEM>>>(QH, QL, KH, KL, VH, VL, AH, AL);

    // out = AO Wo^T + bo  (fp32)
    gemm_out<<<dim3(DD / 128, MTOT / 128), blk, G_SMEM>>>(AH, AL, WoH, WoL, bo, out);
}

// round 11
// speedup vs baseline: 3.7600x; 1.0847x over previous
#include <cuda_runtime.h>
#include <cuda_bf16.h>
#include <cstdint>

// Problem constants
#define BB   4
#define SS   2048
#define DD   1024
#define HH   16
#define DKK  64
#define MTOT (BB*SS)
#define NELEM (MTOT*DD)      // 8388608
#define WELEM (DD*DD)        // 1048576

// Scratch (no cudaMalloc allowed) — all intermediates as bf16 hi/lo pairs
__device__ __nv_bfloat16 g_XQH[NELEM], g_XQL[NELEM];
__device__ __nv_bfloat16 g_XKH[NELEM], g_XKL[NELEM];
__device__ __nv_bfloat16 g_XVH[NELEM], g_XVL[NELEM];
__device__ __nv_bfloat16 g_WqH[WELEM], g_WqL[WELEM];
__device__ __nv_bfloat16 g_WkH[WELEM], g_WkL[WELEM];
__device__ __nv_bfloat16 g_WvH[WELEM], g_WvL[WELEM];
__device__ __nv_bfloat16 g_WoH[WELEM], g_WoL[WELEM];
__device__ __nv_bfloat16 g_QH[NELEM], g_QL[NELEM];
__device__ __nv_bfloat16 g_KH[NELEM], g_KL[NELEM];
__device__ __nv_bfloat16 g_VH[NELEM], g_VL[NELEM];
__device__ __nv_bfloat16 g_AH[NELEM], g_AL[NELEM];

// ---------------------------------------------------------------------------
// Helpers
// ---------------------------------------------------------------------------
__device__ __forceinline__ uint32_t smem_u32(const void* p) {
    uint32_t a;
    asm("{ .reg .u64 t; cvta.to.shared.u64 t, %1; cvt.u32.u64 %0, t; }"
        : "=r"(a) : "l"(p));
    return a;
}

__device__ __forceinline__ void ldm_x4(uint32_t& r0, uint32_t& r1,
                                       uint32_t& r2, uint32_t& r3, uint32_t addr) {
    asm volatile("ldmatrix.sync.aligned.m8n8.x4.shared.b16 {%0,%1,%2,%3}, [%4];"
                 : "=r"(r0), "=r"(r1), "=r"(r2), "=r"(r3) : "r"(addr));
}

__device__ __forceinline__ void ldm_x4_t(uint32_t& r0, uint32_t& r1,
                                         uint32_t& r2, uint32_t& r3, uint32_t addr) {
    asm volatile("ldmatrix.sync.aligned.m8n8.x4.trans.shared.b16 {%0,%1,%2,%3}, [%4];"
                 : "=r"(r0), "=r"(r1), "=r"(r2), "=r"(r3) : "r"(addr));
}

__device__ __forceinline__ void mma16816(float* d,
                                         uint32_t a0, uint32_t a1, uint32_t a2, uint32_t a3,
                                         uint32_t b0, uint32_t b1) {
    asm volatile(
        "mma.sync.aligned.m16n8k16.row.col.f32.bf16.bf16.f32 "
        "{%0,%1,%2,%3}, {%4,%5,%6,%7}, {%8,%9}, {%0,%1,%2,%3};"
        : "+f"(d[0]), "+f"(d[1]), "+f"(d[2]), "+f"(d[3])
        : "r"(a0), "r"(a1), "r"(a2), "r"(a3), "r"(b0), "r"(b1));
}

__device__ __forceinline__ void split2(float x0, float x1, uint32_t& h, uint32_t& l) {
    asm("cvt.rn.bf16x2.f32 %0, %1, %2;" : "=r"(h) : "f"(x1), "f"(x0));
    float h0 = __uint_as_float(h << 16);
    float h1 = __uint_as_float(h & 0xffff0000u);
    asm("cvt.rn.bf16x2.f32 %0, %1, %2;" : "=r"(l) : "f"(x1 - h1), "f"(x0 - h0));
}

__device__ __forceinline__ void cp16(uint32_t s, const void* g) {
    asm volatile("cp.async.cg.shared.global [%0], [%1], 16;" :: "r"(s), "l"(g) : "memory");
}
#define CP_COMMIT() asm volatile("cp.async.commit_group;" ::: "memory")
#define CP_WAIT1()  asm volatile("cp.async.wait_group 1;" ::: "memory")
#define CP_WAIT0()  asm volatile("cp.async.wait_group 0;" ::: "memory")

// ---------------------------------------------------------------------------
// Batched elementwise fp32 -> bf16 hi/lo split: 7 tensors in one launch
// ---------------------------------------------------------------------------
struct SplitBatch {
    const float* src[7];
    __nv_bfloat16* hi[7];
    __nv_bfloat16* lo[7];
    int n4[7];
};

__global__ __launch_bounds__(256) void split_all(SplitBatch sp) {
    const int z = blockIdx.y;
    const int i = blockIdx.x * 256 + threadIdx.x;
    if (i >= sp.n4[z]) return;
    float4 v = ((const float4*)sp.src[z])[i];
    uint32_t h0, l0, h1, l1;
    split2(v.x, v.y, h0, l0);
    split2(v.z, v.w, h1, l1);
    ((uint2*)sp.hi[z])[i] = make_uint2(h0, h1);
    ((uint2*)sp.lo[z])[i] = make_uint2(l0, l1);
}

// ---------------------------------------------------------------------------
// GEMM core: C[8192,1024] = A @ W^T + bias, pre-split bf16 hi/lo operands.
// CTA tile 128x128, BK=32.  SW128 XOR swizzle, zero padding:
//   smem row (128B) = [hi k0..31 | lo k0..31] as 8x16B chunks,
//   physical chunk = c ^ (r & 7).
// 3-stage cp.async pipeline, ONE __syncthreads per K-chunk.
// 8 warps = 4(m) x 2(n); warp tile 32x64, 3 MMA products (hh, hl, lh).
// ---------------------------------------------------------------------------
#define GS_MAT   16384                  // bytes: 128 rows x 128B (hi+lo fused)
#define GS_STAGE (2 * GS_MAT)           // A + W = 32768 B
#define G_SMEM   (3 * GS_STAGE)         // 98304 B -> 2 CTAs/SM

struct GemmBatch {
    const __nv_bfloat16 *Ah[3], *Al[3], *Wh[3], *Wl[3];
    const float* bias[3];
    __nv_bfloat16 *Ch[3], *Cl[3];
    float scale[3];
};

template <typename EPI>
__device__ __forceinline__ void gemm_body(
    const __nv_bfloat16* __restrict__ Ahi, const __nv_bfloat16* __restrict__ Alo,
    const __nv_bfloat16* __restrict__ Whi, const __nv_bfloat16* __restrict__ Wlo,
    EPI epi)
{
    extern __shared__ uint16_t gsm[];
    const uint32_t sb = smem_u32(gsm);

    const int tid  = threadIdx.x;
    const int lane = tid & 31;
    const int wid  = tid >> 5;
    const int wm   = wid & 3;
    const int wn   = wid >> 2;
    const int bm   = blockIdx.y * 128;
    const int bn   = blockIdx.x * 128;

    float acc[2][8][4];
#pragma unroll
    for (int mt = 0; mt < 2; mt++)
#pragma unroll
        for (int nt = 0; nt < 8; nt++)
#pragma unroll
            for (int q = 0; q < 4; q++) acc[mt][nt][q] = 0.f;

    const int a_row = wm * 32 + (lane & 15);      // +mt*16; &7 invariant
    const int a_kh  = (lane >> 4) * 8;            // 0 or 8 (bf16 units)
    const int b_off = (lane & 7) + ((lane & 16) ? 8 : 0);
    const int b_kh  = (lane & 8) ? 8 : 0;
    const uint32_t xkey = (uint32_t)(lane & 7);   // swizzle key for both A and B rows

    // cp.async of one BK=32 chunk into stage s.  2048 16B-chunks, 8/thread.
    auto load_chunk = [&](int ch, int s) {
        const int k0 = ch * 32;
        const uint32_t sbase = sb + (uint32_t)s * GS_STAGE;
#pragma unroll
        for (int it = 0; it < 8; it++) {
            int idx = tid + it * 256;            // 0..2047
            int m   = idx >> 10;                 // 0 = A, 1 = W
            int rem = idx & 1023;
            int r   = rem >> 3;                  // row 0..127
            int c   = rem & 7;                   // logical chunk 0..7
            const __nv_bfloat16* src =
                (m == 0) ? ((c < 4) ? Ahi : Alo) : ((c < 4) ? Whi : Wlo);
            int koff = (c & 3) * 8;
            size_t g = (size_t)((m == 0 ? bm : bn) + r) * DD + k0 + koff;
            uint32_t soff = (uint32_t)(m * GS_MAT) + (uint32_t)(r * 128) +
                            (((uint32_t)c ^ ((uint32_t)r & 7u)) << 4);
            cp16(sbase + soff, src + g);
        }
    };

    load_chunk(0, 0); CP_COMMIT();
    load_chunk(1, 1); CP_COMMIT();

    for (int ch = 0; ch < 32; ch++) {
        if (ch < 31) { CP_WAIT1(); } else { CP_WAIT0(); }
        __syncthreads();
        if (ch + 2 < 32) {                        // prefetch 2 ahead (safe: barrier
            load_chunk(ch + 2, (ch + 2) % 3);     // above covers compute of ch-1)
            CP_COMMIT();
        }

        const uint32_t ss = sb + (uint32_t)(ch % 3) * GS_STAGE;
        const uint32_t sA = ss;
        const uint32_t sW = ss + GS_MAT;

#pragma unroll
        for (int ks = 0; ks < 2; ks++) {
            const int kb = ks * 16;
            const uint32_t chi = (uint32_t)((kb + a_kh) >> 3);   // 0..3
            uint32_t ah[2][4], al[2][4];
#pragma unroll
            for (int mt = 0; mt < 2; mt++) {
                const uint32_t rb = (uint32_t)((a_row + mt * 16) * 128);
                ldm_x4(ah[mt][0], ah[mt][1], ah[mt][2], ah[mt][3],
                       sA + rb + ((chi ^ xkey) << 4));
                ldm_x4(al[mt][0], al[mt][1], al[mt][2], al[mt][3],
                       sA + rb + (((chi + 4) ^ xkey) << 4));
            }
            const uint32_t cbi = (uint32_t)((kb + b_kh) >> 3);
#pragma unroll
            for (int ng = 0; ng < 4; ng++) {
                const uint32_t rb = (uint32_t)((wn * 64 + ng * 16 + b_off) * 128);
                uint32_t bh0, bh1, bh2, bh3, bl0, bl1, bl2, bl3;
                ldm_x4(bh0, bh1, bh2, bh3, sW + rb + ((cbi ^ xkey) << 4));
                ldm_x4(bl0, bl1, bl2, bl3, sW + rb + (((cbi + 4) ^ xkey) << 4));
#pragma unroll
                for (int mt = 0; mt < 2; mt++) {
                    mma16816(acc[mt][2*ng],   ah[mt][0], ah[mt][1], ah[mt][2], ah[mt][3], bh0, bh1);
                    mma16816(acc[mt][2*ng],   ah[mt][0], ah[mt][1], ah[mt][2], ah[mt][3], bl0, bl1);
                    mma16816(acc[mt][2*ng],   al[mt][0], al[mt][1], al[mt][2], al[mt][3], bh0, bh1);
                    mma16816(acc[mt][2*ng+1], ah[mt][0], ah[mt][1], ah[mt][2], ah[mt][3], bh2, bh3);
                    mma16816(acc[mt][2*ng+1], ah[mt][0], ah[mt][1], ah[mt][2], ah[mt][3], bl2, bl3);
                    mma16816(acc[mt][2*ng+1], al[mt][0], al[mt][1], al[mt][2], al[mt][3], bh2, bh3);
                }
            }
        }
    }

#pragma unroll
    for (int mt = 0; mt < 2; mt++) {
#pragma unroll
        for (int nt = 0; nt < 8; nt++) {
            int row = bm + wm * 32 + mt * 16 + (lane >> 2);
            int col = bn + wn * 64 + nt * 8 + (lane & 3) * 2;
            epi(row, col, acc[mt][nt]);
        }
    }
}

// Projections: 3 GEMMs in one launch (z selects), bf16 hi/lo output.
__global__ __launch_bounds__(256, 2) void gemm_proj(GemmBatch gb) {
    const int z = blockIdx.z;
    const __nv_bfloat16* Ahi = gb.Ah[z];
    const __nv_bfloat16* Alo = gb.Al[z];
    const __nv_bfloat16* Whi = gb.Wh[z];
    const __nv_bfloat16* Wlo = gb.Wl[z];
    const float* bias = gb.bias[z];
    __nv_bfloat16* Chi = gb.Ch[z];
    __nv_bfloat16* Clo = gb.Cl[z];
    const float scale = gb.scale[z];

    gemm_body(Ahi, Alo, Whi, Wlo,
        [&](int row, int col, const float* a) {
            float b0 = bias[col], b1 = bias[col + 1];
            uint32_t h, l;
            split2((a[0] + b0) * scale, (a[1] + b1) * scale, h, l);
            *(uint32_t*)(Chi + (size_t)row * DD + col) = h;
            *(uint32_t*)(Clo + (size_t)row * DD + col) = l;
            split2((a[2] + b0) * scale, (a[3] + b1) * scale, h, l);
            *(uint32_t*)(Chi + (size_t)(row + 8) * DD + col) = h;
            *(uint32_t*)(Clo + (size_t)(row + 8) * DD + col) = l;
        });
}

// Final GEMM: fp32 output.
__global__ __launch_bounds__(256, 2) void gemm_out(
    const __nv_bfloat16* __restrict__ Ahi, const __nv_bfloat16* __restrict__ Alo,
    const __nv_bfloat16* __restrict__ Whi, const __nv_bfloat16* __restrict__ Wlo,
    const float* __restrict__ bias, float* __restrict__ Cf)
{
    gemm_body(Ahi, Alo, Whi, Wlo,
        [&](int row, int col, const float* a) {
            float b0 = bias[col], b1 = bias[col + 1];
            *(float2*)(Cf + (size_t)row * DD + col) = make_float2(a[0] + b0, a[1] + b1);
            *(float2*)(Cf + (size_t)(row + 8) * DD + col) = make_float2(a[2] + b0, a[3] + b1);
        });
}

// ---------------------------------------------------------------------------
// Flash attention on HMMA, pre-split bf16 inputs (Q pre-scaled by 1/8).
// CTA: 128 q-rows x one (b,h).  8 warps.  KV tiles of 64, cp.async 2-stage.
// (unchanged from round 10)
// ---------------------------------------------------------------------------
#define AST  72
#define AQH  0
#define AQL  (128 * AST)
#define AKV0 (2 * 128 * AST)
#define TKV  (64 * AST)
#define SKV  (4 * TKV)
#define AT_SMEM ((AKV0 + 2 * SKV) * 2)  // 110592 bytes

__global__ __launch_bounds__(256, 2) void attn_tc(
    const __nv_bfloat16* __restrict__ Qhi, const __nv_bfloat16* __restrict__ Qlo,
    const __nv_bfloat16* __restrict__ Khi, const __nv_bfloat16* __restrict__ Klo,
    const __nv_bfloat16* __restrict__ Vhi, const __nv_bfloat16* __restrict__ Vlo,
    __nv_bfloat16* __restrict__ Ohi, __nv_bfloat16* __restrict__ Olo)
{
    extern __shared__ uint16_t sm16[];
    const uint32_t sb = smem_u32(sm16);

    const int qt = blockIdx.x;
    const int h  = blockIdx.y;
    const int b  = blockIdx.z;

    const int tid  = threadIdx.x;
    const int lane = tid & 31;
    const int wid  = tid >> 5;
    const int m0   = wid * 16;

    const size_t base = ((size_t)b * SS) * DD + (size_t)h * DKK;

    {
        const size_t qb = base + (size_t)(qt * 128) * DD;
#pragma unroll
        for (int it = 0; it < 4; it++) {
            int idx = tid + it * 256;
            int r   = idx >> 3;
            int c   = idx & 7;
            size_t g = qb + (size_t)r * DD + c * 8;
            uint32_t soff = (uint32_t)(r * AST + c * 8) * 2;
            *(uint4*)((char*)sm16 + AQH * 2 + soff) = *(const uint4*)(Qhi + g);
            *(uint4*)((char*)sm16 + AQL * 2 + soff) = *(const uint4*)(Qlo + g);
        }
    }

    auto load_kv = [&](int kt, int s) {
        const size_t kb = base + (size_t)(kt * 64) * DD;
        const uint32_t sbase = sb + (uint32_t)(AKV0 + s * SKV) * 2;
#pragma unroll
        for (int it = 0; it < 2; it++) {
            int idx = tid + it * 256;
            int r   = idx >> 3;
            int c   = idx & 7;
            size_t g = kb + (size_t)r * DD + c * 8;
            uint32_t soff = (uint32_t)(r * AST + c * 8) * 2;
            cp16(sbase + 0 * TKV * 2 + soff, Khi + g);
            cp16(sbase + 1 * TKV * 2 + soff, Klo + g);
            cp16(sbase + 2 * TKV * 2 + soff, Vhi + g);
            cp16(sbase + 3 * TKV * 2 + soff, Vlo + g);
        }
    };

    float o[8][4];
#pragma unroll
    for (int nt = 0; nt < 8; nt++)
#pragma unroll
        for (int q = 0; q < 4; q++) o[nt][q] = 0.f;
    float m0r = -1e30f, m1r = -1e30f, l0r = 0.f, l1r = 0.f;

    const int a_row = m0 + (lane & 15);
    const int a_kh  = (lane >> 4) * 8;
    const int b_off = (lane & 7) + ((lane & 16) ? 8 : 0);
    const int b_kh  = (lane & 8) ? 8 : 0;
    const int v_row = (lane & 15);
    const int v_kh  = (lane & 16) ? 8 : 0;

    load_kv(0, 0);
    CP_COMMIT();

    for (int kt = 0; kt < SS / 64; kt++) {
        if (kt < SS / 64 - 1) {
            load_kv(kt + 1, (kt + 1) & 1);
            CP_COMMIT();
            CP_WAIT1();
        } else {
            CP_WAIT0();
        }
        __syncthreads();

        const uint32_t skv = sb + (uint32_t)(AKV0 + (kt & 1) * SKV) * 2;
        const uint32_t sKH = skv;
        const uint32_t sKL = skv + 1 * TKV * 2;
        const uint32_t sVH = skv + 2 * TKV * 2;
        const uint32_t sVL = skv + 3 * TKV * 2;

        float s[8][4];
#pragma unroll
        for (int nt = 0; nt < 8; nt++)
#pragma unroll
            for (int q = 0; q < 4; q++) s[nt][q] = 0.f;

#pragma unroll
        for (int ks = 0; ks < 4; ks++) {
            const int kb2 = ks * 16;
            uint32_t qh[4], ql[4];
            uint32_t qoff = (uint32_t)(a_row * AST + kb2 + a_kh) * 2;
            ldm_x4(qh[0], qh[1], qh[2], qh[3], sb + AQH * 2 + qoff);
            ldm_x4(ql[0], ql[1], ql[2], ql[3], sb + AQL * 2 + qoff);
#pragma unroll
            for (int ng = 0; ng < 4; ng++) {
                uint32_t koff = (uint32_t)((ng * 16 + b_off) * AST + kb2 + b_kh) * 2;
                uint32_t kh0, kh1, kh2, kh3, kl0, kl1, kl2, kl3;
                ldm_x4(kh0, kh1, kh2, kh3, sKH + koff);
                ldm_x4(kl0, kl1, kl2, kl3, sKL + koff);
                mma16816(s[2*ng],   qh[0], qh[1], qh[2], qh[3], kh0, kh1);
                mma16816(s[2*ng],   qh[0], qh[1], qh[2], qh[3], kl0, kl1);
                mma16816(s[2*ng],   ql[0], ql[1], ql[2], ql[3], kh0, kh1);
                mma16816(s[2*ng+1], qh[0], qh[1], qh[2], qh[3], kh2, kh3);
                mma16816(s[2*ng+1], qh[0], qh[1], qh[2], qh[3], kl2, kl3);
                mma16816(s[2*ng+1], ql[0], ql[1], ql[2], ql[3], kh2, kh3);
            }
        }

        float mx0 = -1e30f, mx1 = -1e30f;
#pragma unroll
        for (int nt = 0; nt < 8; nt++) {
            mx0 = fmaxf(mx0, fmaxf(s[nt][0], s[nt][1]));
            mx1 = fmaxf(mx1, fmaxf(s[nt][2], s[nt][3]));
        }
#pragma unroll
        for (int off = 1; off <= 2; off <<= 1) {
            mx0 = fmaxf(mx0, __shfl_xor_sync(0xffffffffu, mx0, off));
            mx1 = fmaxf(mx1, __shfl_xor_sync(0xffffffffu, mx1, off));
        }
        float mn0 = fmaxf(m0r, mx0), mn1 = fmaxf(m1r, mx1);
        float al0 = __expf(m0r - mn0), al1 = __expf(m1r - mn1);
        m0r = mn0; m1r = mn1;

        float sum0 = 0.f, sum1 = 0.f;
#pragma unroll
        for (int nt = 0; nt < 8; nt++) {
            s[nt][0] = __expf(s[nt][0] - mn0);
            s[nt][1] = __expf(s[nt][1] - mn0);
            s[nt][2] = __expf(s[nt][2] - mn1);
            s[nt][3] = __expf(s[nt][3] - mn1);
            sum0 += s[nt][0] + s[nt][1];
            sum1 += s[nt][2] + s[nt][3];
        }
#pragma unroll
        for (int off = 1; off <= 2; off <<= 1) {
            sum0 += __shfl_xor_sync(0xffffffffu, sum0, off);
            sum1 += __shfl_xor_sync(0xffffffffu, sum1, off);
        }
        l0r = l0r * al0 + sum0;
        l1r = l1r * al1 + sum1;
#pragma unroll
        for (int nt = 0; nt < 8; nt++) {
            o[nt][0] *= al0; o[nt][1] *= al0;
            o[nt][2] *= al1; o[nt][3] *= al1;
        }

#pragma unroll
        for (int ksj = 0; ksj < 4; ksj++) {
            uint32_t ph0, pl0, ph1, pl1, ph2, pl2, ph3, pl3;
            split2(s[2*ksj][0],   s[2*ksj][1],   ph0, pl0);
            split2(s[2*ksj][2],   s[2*ksj][3],   ph1, pl1);
            split2(s[2*ksj+1][0], s[2*ksj+1][1], ph2, pl2);
            split2(s[2*ksj+1][2], s[2*ksj+1][3], ph3, pl3);
#pragma unroll
            for (int ng = 0; ng < 4; ng++) {
                uint32_t voff = (uint32_t)((ksj * 16 + v_row) * AST + ng * 16 + v_kh) * 2;
                uint32_t vh0, vh1, vh2, vh3, vl0, vl1, vl2, vl3;
                ldm_x4_t(vh0, vh1, vh2, vh3, sVH + voff);
                ldm_x4_t(vl0, vl1, vl2, vl3, sVL + voff);
                mma16816(o[2*ng],   ph0, ph1, ph2, ph3, vh0, vh1);
                mma16816(o[2*ng],   ph0, ph1, ph2, ph3, vl0, vl1);
                mma16816(o[2*ng],   pl0, pl1, pl2, pl3, vh0, vh1);
                mma16816(o[2*ng+1], ph0, ph1, ph2, ph3, vh2, vh3);
                mma16816(o[2*ng+1], ph0, ph1, ph2, ph3, vl2, vl3);
                mma16816(o[2*ng+1], pl0, pl1, pl2, pl3, vh2, vh3);
            }
        }
        __syncthreads();
    }

    float inv0 = 1.f / l0r, inv1 = 1.f / l1r;
    const int row0 = qt * 128 + m0 + (lane >> 2);
#pragma unroll
    for (int nt = 0; nt < 8; nt++) {
        int col = nt * 8 + (lane & 3) * 2;
        uint32_t h2, l2;
        split2(o[nt][0] * inv0, o[nt][1] * inv0, h2, l2);
        *(uint32_t*)(Ohi + base + (size_t)row0 * DD + col) = h2;
        *(uint32_t*)(Olo + base + (size_t)row0 * DD + col) = l2;
        split2(o[nt][2] * inv1, o[nt][3] * inv1, h2, l2);
        *(uint32_t*)(Ohi + base + (size_t)(row0 + 8) * DD + col) = h2;
        *(uint32_t*)(Olo + base + (size_t)(row0 + 8) * DD + col) = l2;
    }
}

// ---------------------------------------------------------------------------
// Launch
// ---------------------------------------------------------------------------
extern "C" void kernel_launch(void* const* d_in, const int* in_sizes, int n_in,
                              void* d_out, int out_size)
{
    const float* xQ = (const float*)d_in[0];
    const float* xK = (const float*)d_in[1];
    const float* xV = (const float*)d_in[2];
    const float* Wq = (const float*)d_in[3];
    const float* bq = (const float*)d_in[4];
    const float* Wk = (const float*)d_in[5];
    const float* bk = (const float*)d_in[6];
    const float* Wv = (const float*)d_in[7];
    const float* bv = (const float*)d_in[8];
    const float* Wo = (const float*)d_in[9];
    const float* bo = (const float*)d_in[10];
    float* out = (float*)d_out;

    __nv_bfloat16 *XQH,*XQL,*XKH,*XKL,*XVH,*XVL;
    __nv_bfloat16 *WqH,*WqL,*WkH,*WkL,*WvH,*WvL,*WoH,*WoL;
    __nv_bfloat16 *QH,*QL,*KH,*KL,*VH,*VL,*AH,*AL;
    cudaGetSymbolAddress((void**)&XQH, g_XQH); cudaGetSymbolAddress((void**)&XQL, g_XQL);
    cudaGetSymbolAddress((void**)&XKH, g_XKH); cudaGetSymbolAddress((void**)&XKL, g_XKL);
    cudaGetSymbolAddress((void**)&XVH, g_XVH); cudaGetSymbolAddress((void**)&XVL, g_XVL);
    cudaGetSymbolAddress((void**)&WqH, g_WqH); cudaGetSymbolAddress((void**)&WqL, g_WqL);
    cudaGetSymbolAddress((void**)&WkH, g_WkH); cudaGetSymbolAddress((void**)&WkL, g_WkL);
    cudaGetSymbolAddress((void**)&WvH, g_WvH); cudaGetSymbolAddress((void**)&WvL, g_WvL);
    cudaGetSymbolAddress((void**)&WoH, g_WoH); cudaGetSymbolAddress((void**)&WoL, g_WoL);
    cudaGetSymbolAddress((void**)&QH,  g_QH);  cudaGetSymbolAddress((void**)&QL,  g_QL);
    cudaGetSymbolAddress((void**)&KH,  g_KH);  cudaGetSymbolAddress((void**)&KL,  g_KL);
    cudaGetSymbolAddress((void**)&VH,  g_VH);  cudaGetSymbolAddress((void**)&VL,  g_VL);
    cudaGetSymbolAddress((void**)&AH,  g_AH);  cudaGetSymbolAddress((void**)&AL,  g_AL);

    cudaFuncSetAttribute(gemm_proj,
                         cudaFuncAttributeMaxDynamicSharedMemorySize, G_SMEM);
    cudaFuncSetAttribute(gemm_out,
                         cudaFuncAttributeMaxDynamicSharedMemorySize, G_SMEM);
    cudaFuncSetAttribute(attn_tc,
                         cudaFuncAttributeMaxDynamicSharedMemorySize, AT_SMEM);

    dim3 blk(256);
    const int nX = NELEM / 4, nW = WELEM / 4;

    // All 7 splits in one launch
    SplitBatch sp;
    sp.src[0]=xQ; sp.hi[0]=XQH; sp.lo[0]=XQL; sp.n4[0]=nX;
    sp.src[1]=xK; sp.hi[1]=XKH; sp.lo[1]=XKL; sp.n4[1]=nX;
    sp.src[2]=xV; sp.hi[2]=XVH; sp.lo[2]=XVL; sp.n4[2]=nX;
    sp.src[3]=Wq; sp.hi[3]=WqH; sp.lo[3]=WqL; sp.n4[3]=nW;
    sp.src[4]=Wk; sp.hi[4]=WkH; sp.lo[4]=WkL; sp.n4[4]=nW;
    sp.src[5]=Wv; sp.hi[5]=WvH; sp.lo[5]=WvL; sp.n4[5]=nW;
    sp.src[6]=Wo; sp.hi[6]=WoH; sp.lo[6]=WoL; sp.n4[6]=nW;
    split_all<<<dim3((nX + 255) / 256, 7), blk>>>(sp);

    // 3 projection GEMMs in one launch
    GemmBatch gb;
    gb.Ah[0]=XQH; gb.Al[0]=XQL; gb.Wh[0]=WqH; gb.Wl[0]=WqL; gb.bias[0]=bq;
    gb.Ch[0]=QH;  gb.Cl[0]=QL;  gb.scale[0]=0.125f;
    gb.Ah[1]=XKH; gb.Al[1]=XKL; gb.Wh[1]=WkH; gb.Wl[1]=WkL; gb.bias[1]=bk;
    gb.Ch[1]=KH;  gb.Cl[1]=KL;  gb.scale[1]=1.0f;
    gb.Ah[2]=XVH; gb.Al[2]=XVL; gb.Wh[2]=WvH; gb.Wl[2]=WvL; gb.bias[2]=bv;
    gb.Ch[2]=VH;  gb.Cl[2]=VL;  gb.scale[2]=1.0f;
    gemm_proj<<<dim3(DD / 128, MTOT / 128, 3), blk, G_SMEM>>>(gb);

    // Attention
    dim3 agrid(SS / 128, HH, BB);           // (16, 16, 4)
    attn_tc<<<agrid, blk, AT_SMEM>>>(QH, QL, KH, KL, VH, VL, AH, AL);

    // out = AO Wo^T + bo  (fp32)
    gemm_out<<<dim3(DD / 128, MTOT / 128), blk, G_SMEM>>>(AH, AL, WoH, WoL, bo, out);
}

// round 12
// speedup vs baseline: 4.3144x; 1.1475x over previous
#include <cuda_runtime.h>
#include <cuda_bf16.h>
#include <cuda_fp16.h>
#include <cstdint>

// Problem constants
#define BB   4
#define SS   2048
#define DD   1024
#define HH   16
#define DKK  64
#define MTOT (BB*SS)
#define NELEM (MTOT*DD)      // 8388608
#define WELEM (DD*DD)        // 1048576

// Scratch (no cudaMalloc allowed)
__device__ __nv_bfloat16 g_XQH[NELEM], g_XQL[NELEM];
__device__ __nv_bfloat16 g_XKH[NELEM], g_XKL[NELEM];
__device__ __nv_bfloat16 g_XVH[NELEM], g_XVL[NELEM];
__device__ __nv_bfloat16 g_WqH[WELEM], g_WqL[WELEM];
__device__ __nv_bfloat16 g_WkH[WELEM], g_WkL[WELEM];
__device__ __nv_bfloat16 g_WvH[WELEM], g_WvL[WELEM];
__device__ __nv_bfloat16 g_WoH[WELEM], g_WoL[WELEM];
__device__ __nv_bfloat16 g_QH[NELEM], g_QL[NELEM];
__device__ __nv_bfloat16 g_KH[NELEM], g_KL[NELEM];
__device__ __half        g_V16[NELEM];               // V as direct fp16
__device__ __nv_bfloat16 g_AH[NELEM], g_AL[NELEM];

// ---------------------------------------------------------------------------
// Helpers
// ---------------------------------------------------------------------------
__device__ __forceinline__ uint32_t smem_u32(const void* p) {
    uint32_t a;
    asm("{ .reg .u64 t; cvta.to.shared.u64 t, %1; cvt.u32.u64 %0, t; }"
        : "=r"(a) : "l"(p));
    return a;
}

__device__ __forceinline__ void ldm_x4(uint32_t& r0, uint32_t& r1,
                                       uint32_t& r2, uint32_t& r3, uint32_t addr) {
    asm volatile("ldmatrix.sync.aligned.m8n8.x4.shared.b16 {%0,%1,%2,%3}, [%4];"
                 : "=r"(r0), "=r"(r1), "=r"(r2), "=r"(r3) : "r"(addr));
}

__device__ __forceinline__ void ldm_x4_t(uint32_t& r0, uint32_t& r1,
                                         uint32_t& r2, uint32_t& r3, uint32_t addr) {
    asm volatile("ldmatrix.sync.aligned.m8n8.x4.trans.shared.b16 {%0,%1,%2,%3}, [%4];"
                 : "=r"(r0), "=r"(r1), "=r"(r2), "=r"(r3) : "r"(addr));
}

// bf16 MMA
__device__ __forceinline__ void mma16816(float* d,
                                         uint32_t a0, uint32_t a1, uint32_t a2, uint32_t a3,
                                         uint32_t b0, uint32_t b1) {
    asm volatile(
        "mma.sync.aligned.m16n8k16.row.col.f32.bf16.bf16.f32 "
        "{%0,%1,%2,%3}, {%4,%5,%6,%7}, {%8,%9}, {%0,%1,%2,%3};"
        : "+f"(d[0]), "+f"(d[1]), "+f"(d[2]), "+f"(d[3])
        : "r"(a0), "r"(a1), "r"(a2), "r"(a3), "r"(b0), "r"(b1));
}

// fp16 MMA
__device__ __forceinline__ void mma16816h(float* d,
                                          uint32_t a0, uint32_t a1, uint32_t a2, uint32_t a3,
                                          uint32_t b0, uint32_t b1) {
    asm volatile(
        "mma.sync.aligned.m16n8k16.row.col.f32.f16.f16.f32 "
        "{%0,%1,%2,%3}, {%4,%5,%6,%7}, {%8,%9}, {%0,%1,%2,%3};"
        : "+f"(d[0]), "+f"(d[1]), "+f"(d[2]), "+f"(d[3])
        : "r"(a0), "r"(a1), "r"(a2), "r"(a3), "r"(b0), "r"(b1));
}

__device__ __forceinline__ void split2(float x0, float x1, uint32_t& h, uint32_t& l) {
    asm("cvt.rn.bf16x2.f32 %0, %1, %2;" : "=r"(h) : "f"(x1), "f"(x0));
    float h0 = __uint_as_float(h << 16);
    float h1 = __uint_as_float(h & 0xffff0000u);
    asm("cvt.rn.bf16x2.f32 %0, %1, %2;" : "=r"(l) : "f"(x1 - h1), "f"(x0 - h0));
}

__device__ __forceinline__ uint32_t packh2(float x0, float x1) {
    uint32_t r;
    asm("cvt.rn.f16x2.f32 %0, %1, %2;" : "=r"(r) : "f"(x1), "f"(x0));
    return r;
}

__device__ __forceinline__ void cp16(uint32_t s, const void* g) {
    asm volatile("cp.async.cg.shared.global [%0], [%1], 16;" :: "r"(s), "l"(g) : "memory");
}
#define CP_COMMIT() asm volatile("cp.async.commit_group;" ::: "memory")
#define CP_WAIT1()  asm volatile("cp.async.wait_group 1;" ::: "memory")
#define CP_WAIT0()  asm volatile("cp.async.wait_group 0;" ::: "memory")

// ---------------------------------------------------------------------------
// Batched elementwise fp32 -> bf16 hi/lo split: 7 tensors in one launch
// ---------------------------------------------------------------------------
struct SplitBatch {
    const float* src[7];
    __nv_bfloat16* hi[7];
    __nv_bfloat16* lo[7];
    int n4[7];
};

__global__ __launch_bounds__(256) void split_all(SplitBatch sp) {
    const int z = blockIdx.y;
    const int i = blockIdx.x * 256 + threadIdx.x;
    if (i >= sp.n4[z]) return;
    float4 v = ((const float4*)sp.src[z])[i];
    uint32_t h0, l0, h1, l1;
    split2(v.x, v.y, h0, l0);
    split2(v.z, v.w, h1, l1);
    ((uint2*)sp.hi[z])[i] = make_uint2(h0, h1);
    ((uint2*)sp.lo[z])[i] = make_uint2(l0, l1);
}

// ---------------------------------------------------------------------------
// GEMM core (unchanged from round 11): 128x128 tile, BK=32, XOR-swizzled,
// 3-stage cp.async, one barrier per chunk, bf16 3-product split.
// ---------------------------------------------------------------------------
#define GS_MAT   16384
#define GS_STAGE (2 * GS_MAT)
#define G_SMEM   (3 * GS_STAGE)         // 98304 B

struct GemmBatch {
    const __nv_bfloat16 *Ah[3], *Al[3], *Wh[3], *Wl[3];
    const float* bias[3];
    void* Co[3];          // z<2: bf16 hi buffer; z==2: fp16 buffer
    __nv_bfloat16* Cl[3]; // z<2 only
    float scale[3];
};

template <typename EPI>
__device__ __forceinline__ void gemm_body(
    const __nv_bfloat16* __restrict__ Ahi, const __nv_bfloat16* __restrict__ Alo,
    const __nv_bfloat16* __restrict__ Whi, const __nv_bfloat16* __restrict__ Wlo,
    EPI epi)
{
    extern __shared__ uint16_t gsm[];
    const uint32_t sb = smem_u32(gsm);

    const int tid  = threadIdx.x;
    const int lane = tid & 31;
    const int wid  = tid >> 5;
    const int wm   = wid & 3;
    const int wn   = wid >> 2;
    const int bm   = blockIdx.y * 128;
    const int bn   = blockIdx.x * 128;

    float acc[2][8][4];
#pragma unroll
    for (int mt = 0; mt < 2; mt++)
#pragma unroll
        for (int nt = 0; nt < 8; nt++)
#pragma unroll
            for (int q = 0; q < 4; q++) acc[mt][nt][q] = 0.f;

    const int a_row = wm * 32 + (lane & 15);
    const int a_kh  = (lane >> 4) * 8;
    const int b_off = (lane & 7) + ((lane & 16) ? 8 : 0);
    const int b_kh  = (lane & 8) ? 8 : 0;
    const uint32_t xkey = (uint32_t)(lane & 7);

    auto load_chunk = [&](int ch, int s) {
        const int k0 = ch * 32;
        const uint32_t sbase = sb + (uint32_t)s * GS_STAGE;
#pragma unroll
        for (int it = 0; it < 8; it++) {
            int idx = tid + it * 256;
            int m   = idx >> 10;
            int rem = idx & 1023;
            int r   = rem >> 3;
            int c   = rem & 7;
            const __nv_bfloat16* src =
                (m == 0) ? ((c < 4) ? Ahi : Alo) : ((c < 4) ? Whi : Wlo);
            int koff = (c & 3) * 8;
            size_t g = (size_t)((m == 0 ? bm : bn) + r) * DD + k0 + koff;
            uint32_t soff = (uint32_t)(m * GS_MAT) + (uint32_t)(r * 128) +
                            (((uint32_t)c ^ ((uint32_t)r & 7u)) << 4);
            cp16(sbase + soff, src + g);
        }
    };

    load_chunk(0, 0); CP_COMMIT();
    load_chunk(1, 1); CP_COMMIT();

    for (int ch = 0; ch < 32; ch++) {
        if (ch < 31) { CP_WAIT1(); } else { CP_WAIT0(); }
        __syncthreads();
        if (ch + 2 < 32) {
            load_chunk(ch + 2, (ch + 2) % 3);
            CP_COMMIT();
        }

        const uint32_t ss = sb + (uint32_t)(ch % 3) * GS_STAGE;
        const uint32_t sA = ss;
        const uint32_t sW = ss + GS_MAT;

#pragma unroll
        for (int ks = 0; ks < 2; ks++) {
            const int kb = ks * 16;
            const uint32_t chi = (uint32_t)((kb + a_kh) >> 3);
            uint32_t ah[2][4], al[2][4];
#pragma unroll
            for (int mt = 0; mt < 2; mt++) {
                const uint32_t rb = (uint32_t)((a_row + mt * 16) * 128);
                ldm_x4(ah[mt][0], ah[mt][1], ah[mt][2], ah[mt][3],
                       sA + rb + ((chi ^ xkey) << 4));
                ldm_x4(al[mt][0], al[mt][1], al[mt][2], al[mt][3],
                       sA + rb + (((chi + 4) ^ xkey) << 4));
            }
            const uint32_t cbi = (uint32_t)((kb + b_kh) >> 3);
#pragma unroll
            for (int ng = 0; ng < 4; ng++) {
                const uint32_t rb = (uint32_t)((wn * 64 + ng * 16 + b_off) * 128);
                uint32_t bh0, bh1, bh2, bh3, bl0, bl1, bl2, bl3;
                ldm_x4(bh0, bh1, bh2, bh3, sW + rb + ((cbi ^ xkey) << 4));
                ldm_x4(bl0, bl1, bl2, bl3, sW + rb + (((cbi + 4) ^ xkey) << 4));
#pragma unroll
                for (int mt = 0; mt < 2; mt++) {
                    mma16816(acc[mt][2*ng],   ah[mt][0], ah[mt][1], ah[mt][2], ah[mt][3], bh0, bh1);
                    mma16816(acc[mt][2*ng],   ah[mt][0], ah[mt][1], ah[mt][2], ah[mt][3], bl0, bl1);
                    mma16816(acc[mt][2*ng],   al[mt][0], al[mt][1], al[mt][2], al[mt][3], bh0, bh1);
                    mma16816(acc[mt][2*ng+1], ah[mt][0], ah[mt][1], ah[mt][2], ah[mt][3], bh2, bh3);
                    mma16816(acc[mt][2*ng+1], ah[mt][0], ah[mt][1], ah[mt][2], ah[mt][3], bl2, bl3);
                    mma16816(acc[mt][2*ng+1], al[mt][0], al[mt][1], al[mt][2], al[mt][3], bh2, bh3);
                }
            }
        }
    }

#pragma unroll
    for (int mt = 0; mt < 2; mt++) {
#pragma unroll
        for (int nt = 0; nt < 8; nt++) {
            int row = bm + wm * 32 + mt * 16 + (lane >> 2);
            int col = bn + wn * 64 + nt * 8 + (lane & 3) * 2;
            epi(row, col, acc[mt][nt]);
        }
    }
}

// Projections: 3 GEMMs in one launch.  z 0,1 (Q,K): bf16 hi/lo out.
// z 2 (V): direct fp16 out (feeds the single-product PV MMA).
__global__ __launch_bounds__(256, 2) void gemm_proj(GemmBatch gb) {
    const int z = blockIdx.z;
    const __nv_bfloat16* Ahi = gb.Ah[z];
    const __nv_bfloat16* Alo = gb.Al[z];
    const __nv_bfloat16* Whi = gb.Wh[z];
    const __nv_bfloat16* Wlo = gb.Wl[z];
    const float* bias = gb.bias[z];
    __nv_bfloat16* Chi = (__nv_bfloat16*)gb.Co[z];
    __half*        C16 = (__half*)gb.Co[z];
    __nv_bfloat16* Clo = gb.Cl[z];
    const float scale = gb.scale[z];

    gemm_body(Ahi, Alo, Whi, Wlo,
        [&](int row, int col, const float* a) {
            float b0 = bias[col], b1 = bias[col + 1];
            float v0 = (a[0] + b0) * scale, v1 = (a[1] + b1) * scale;
            float v2 = (a[2] + b0) * scale, v3 = (a[3] + b1) * scale;
            if (z == 2) {
                *(uint32_t*)(C16 + (size_t)row * DD + col)       = packh2(v0, v1);
                *(uint32_t*)(C16 + (size_t)(row + 8) * DD + col) = packh2(v2, v3);
            } else {
                uint32_t h, l;
                split2(v0, v1, h, l);
                *(uint32_t*)(Chi + (size_t)row * DD + col) = h;
                *(uint32_t*)(Clo + (size_t)row * DD + col) = l;
                split2(v2, v3, h, l);
                *(uint32_t*)(Chi + (size_t)(row + 8) * DD + col) = h;
                *(uint32_t*)(Clo + (size_t)(row + 8) * DD + col) = l;
            }
        });
}

// Final GEMM: fp32 output.
__global__ __launch_bounds__(256, 2) void gemm_out(
    const __nv_bfloat16* __restrict__ Ahi, const __nv_bfloat16* __restrict__ Alo,
    const __nv_bfloat16* __restrict__ Whi, const __nv_bfloat16* __restrict__ Wlo,
    const float* __restrict__ bias, float* __restrict__ Cf)
{
    gemm_body(Ahi, Alo, Whi, Wlo,
        [&](int row, int col, const float* a) {
            float b0 = bias[col], b1 = bias[col + 1];
            *(float2*)(Cf + (size_t)row * DD + col) = make_float2(a[0] + b0, a[1] + b1);
            *(float2*)(Cf + (size_t)(row + 8) * DD + col) = make_float2(a[2] + b0, a[3] + b1);
        });
}

// ---------------------------------------------------------------------------
// Flash attention.  QK^T: bf16-split (3 products).  PV: direct fp16
// (1 product; fp16 is 8x finer than bf16 -> PV error ~2.6e-4, budget 1e-3).
// KV stage = {Khi, Klo, V16}: 3 arrays, cp.async 2-stage.
// ---------------------------------------------------------------------------
#define AST  72
#define AQH  0
#define AQL  (128 * AST)
#define AKV0 (2 * 128 * AST)
#define TKV  (64 * AST)
#define SKV  (3 * TKV)
#define AT_SMEM ((AKV0 + 2 * SKV) * 2)  // 92160 bytes

__global__ __launch_bounds__(256, 2) void attn_tc(
    const __nv_bfloat16* __restrict__ Qhi, const __nv_bfloat16* __restrict__ Qlo,
    const __nv_bfloat16* __restrict__ Khi, const __nv_bfloat16* __restrict__ Klo,
    const __half* __restrict__ V16,
    __nv_bfloat16* __restrict__ Ohi, __nv_bfloat16* __restrict__ Olo)
{
    extern __shared__ uint16_t sm16[];
    const uint32_t sb = smem_u32(sm16);

    const int qt = blockIdx.x;
    const int h  = blockIdx.y;
    const int b  = blockIdx.z;

    const int tid  = threadIdx.x;
    const int lane = tid & 31;
    const int wid  = tid >> 5;
    const int m0   = wid * 16;

    const size_t base = ((size_t)b * SS) * DD + (size_t)h * DKK;

    {
        const size_t qb = base + (size_t)(qt * 128) * DD;
#pragma unroll
        for (int it = 0; it < 4; it++) {
            int idx = tid + it * 256;
            int r   = idx >> 3;
            int c   = idx & 7;
            size_t g = qb + (size_t)r * DD + c * 8;
            uint32_t soff = (uint32_t)(r * AST + c * 8) * 2;
            *(uint4*)((char*)sm16 + AQH * 2 + soff) = *(const uint4*)(Qhi + g);
            *(uint4*)((char*)sm16 + AQL * 2 + soff) = *(const uint4*)(Qlo + g);
        }
    }

    auto load_kv = [&](int kt, int s) {
        const size_t kb = base + (size_t)(kt * 64) * DD;
        const uint32_t sbase = sb + (uint32_t)(AKV0 + s * SKV) * 2;
#pragma unroll
        for (int it = 0; it < 2; it++) {
            int idx = tid + it * 256;
            int r   = idx >> 3;
            int c   = idx & 7;
            size_t g = kb + (size_t)r * DD + c * 8;
            uint32_t soff = (uint32_t)(r * AST + c * 8) * 2;
            cp16(sbase + 0 * TKV * 2 + soff, Khi + g);
            cp16(sbase + 1 * TKV * 2 + soff, Klo + g);
            cp16(sbase + 2 * TKV * 2 + soff, V16 + g);
        }
    };

    float o[8][4];
#pragma unroll
    for (int nt = 0; nt < 8; nt++)
#pragma unroll
        for (int q = 0; q < 4; q++) o[nt][q] = 0.f;
    float m0r = -1e30f, m1r = -1e30f, l0r = 0.f, l1r = 0.f;

    const int a_row = m0 + (lane & 15);
    const int a_kh  = (lane >> 4) * 8;
    const int b_off = (lane & 7) + ((lane & 16) ? 8 : 0);
    const int b_kh  = (lane & 8) ? 8 : 0;
    const int v_row = (lane & 15);
    const int v_kh  = (lane & 16) ? 8 : 0;

    load_kv(0, 0);
    CP_COMMIT();

    for (int kt = 0; kt < SS / 64; kt++) {
        if (kt < SS / 64 - 1) {
            load_kv(kt + 1, (kt + 1) & 1);
            CP_COMMIT();
            CP_WAIT1();
        } else {
            CP_WAIT0();
        }
        __syncthreads();

        const uint32_t skv = sb + (uint32_t)(AKV0 + (kt & 1) * SKV) * 2;
        const uint32_t sKH = skv;
        const uint32_t sKL = skv + 1 * TKV * 2;
        const uint32_t sV  = skv + 2 * TKV * 2;

        // S = Q K^T  (bf16 split, 3 products)
        float s[8][4];
#pragma unroll
        for (int nt = 0; nt < 8; nt++)
#pragma unroll
            for (int q = 0; q < 4; q++) s[nt][q] = 0.f;

#pragma unroll
        for (int ks = 0; ks < 4; ks++) {
            const int kb2 = ks * 16;
            uint32_t qh[4], ql[4];
            uint32_t qoff = (uint32_t)(a_row * AST + kb2 + a_kh) * 2;
            ldm_x4(qh[0], qh[1], qh[2], qh[3], sb + AQH * 2 + qoff);
            ldm_x4(ql[0], ql[1], ql[2], ql[3], sb + AQL * 2 + qoff);
#pragma unroll
            for (int ng = 0; ng < 4; ng++) {
                uint32_t koff = (uint32_t)((ng * 16 + b_off) * AST + kb2 + b_kh) * 2;
                uint32_t kh0, kh1, kh2, kh3, kl0, kl1, kl2, kl3;
                ldm_x4(kh0, kh1, kh2, kh3, sKH + koff);
                ldm_x4(kl0, kl1, kl2, kl3, sKL + koff);
                mma16816(s[2*ng],   qh[0], qh[1], qh[2], qh[3], kh0, kh1);
                mma16816(s[2*ng],   qh[0], qh[1], qh[2], qh[3], kl0, kl1);
                mma16816(s[2*ng],   ql[0], ql[1], ql[2], ql[3], kh0, kh1);
                mma16816(s[2*ng+1], qh[0], qh[1], qh[2], qh[3], kh2, kh3);
                mma16816(s[2*ng+1], qh[0], qh[1], qh[2], qh[3], kl2, kl3);
                mma16816(s[2*ng+1], ql[0], ql[1], ql[2], ql[3], kh2, kh3);
            }
        }

        // Online softmax in C-fragments
        float mx0 = -1e30f, mx1 = -1e30f;
#pragma unroll
        for (int nt = 0; nt < 8; nt++) {
            mx0 = fmaxf(mx0, fmaxf(s[nt][0], s[nt][1]));
            mx1 = fmaxf(mx1, fmaxf(s[nt][2], s[nt][3]));
        }
#pragma unroll
        for (int off = 1; off <= 2; off <<= 1) {
            mx0 = fmaxf(mx0, __shfl_xor_sync(0xffffffffu, mx0, off));
            mx1 = fmaxf(mx1, __shfl_xor_sync(0xffffffffu, mx1, off));
        }
        float mn0 = fmaxf(m0r, mx0), mn1 = fmaxf(m1r, mx1);
        float al0 = __expf(m0r - mn0), al1 = __expf(m1r - mn1);
        m0r = mn0; m1r = mn1;

        float sum0 = 0.f, sum1 = 0.f;
#pragma unroll
        for (int nt = 0; nt < 8; nt++) {
            s[nt][0] = __expf(s[nt][0] - mn0);
            s[nt][1] = __expf(s[nt][1] - mn0);
            s[nt][2] = __expf(s[nt][2] - mn1);
            s[nt][3] = __expf(s[nt][3] - mn1);
            sum0 += s[nt][0] + s[nt][1];
            sum1 += s[nt][2] + s[nt][3];
        }
#pragma unroll
        for (int off = 1; off <= 2; off <<= 1) {
            sum0 += __shfl_xor_sync(0xffffffffu, sum0, off);
            sum1 += __shfl_xor_sync(0xffffffffu, sum1, off);
        }
        l0r = l0r * al0 + sum0;
        l1r = l1r * al1 + sum1;
#pragma unroll
        for (int nt = 0; nt < 8; nt++) {
            o[nt][0] *= al0; o[nt][1] *= al0;
            o[nt][2] *= al1; o[nt][3] *= al1;
        }

        // O += P V  (direct fp16, single product)
#pragma unroll
        for (int ksj = 0; ksj < 4; ksj++) {
            uint32_t pa0 = packh2(s[2*ksj][0],   s[2*ksj][1]);
            uint32_t pa1 = packh2(s[2*ksj][2],   s[2*ksj][3]);
            uint32_t pa2 = packh2(s[2*ksj+1][0], s[2*ksj+1][1]);
            uint32_t pa3 = packh2(s[2*ksj+1][2], s[2*ksj+1][3]);
#pragma unroll
            for (int ng = 0; ng < 4; ng++) {
                uint32_t voff = (uint32_t)((ksj * 16 + v_row) * AST + ng * 16 + v_kh) * 2;
                uint32_t v0, v1, v2, v3;
                ldm_x4_t(v0, v1, v2, v3, sV + voff);
                mma16816h(o[2*ng],   pa0, pa1, pa2, pa3, v0, v1);
                mma16816h(o[2*ng+1], pa0, pa1, pa2, pa3, v2, v3);
            }
        }
        __syncthreads();
    }

    // Normalize + store as bf16 hi/lo
    float inv0 = 1.f / l0r, inv1 = 1.f / l1r;
    const int row0 = qt * 128 + m0 + (lane >> 2);
#pragma unroll
    for (int nt = 0; nt < 8; nt++) {
        int col = nt * 8 + (lane & 3) * 2;
        uint32_t h2, l2;
        split2(o[nt][0] * inv0, o[nt][1] * inv0, h2, l2);
        *(uint32_t*)(Ohi + base + (size_t)row0 * DD + col) = h2;
        *(uint32_t*)(Olo + base + (size_t)row0 * DD + col) = l2;
        split2(o[nt][2] * inv1, o[nt][3] * inv1, h2, l2);
        *(uint32_t*)(Ohi + base + (size_t)(row0 + 8) * DD + col) = h2;
        *(uint32_t*)(Olo + base + (size_t)(row0 + 8) * DD + col) = l2;
    }
}

// ---------------------------------------------------------------------------
// Launch
// ---------------------------------------------------------------------------
extern "C" void kernel_launch(void* const* d_in, const int* in_sizes, int n_in,
                              void* d_out, int out_size)
{
    const float* xQ = (const float*)d_in[0];
    const float* xK = (const float*)d_in[1];
    const float* xV = (const float*)d_in[2];
    const float* Wq = (const float*)d_in[3];
    const float* bq = (const float*)d_in[4];
    const float* Wk = (const float*)d_in[5];
    const float* bk = (const float*)d_in[6];
    const float* Wv = (const float*)d_in[7];
    const float* bv = (const float*)d_in[8];
    const float* Wo = (const float*)d_in[9];
    const float* bo = (const float*)d_in[10];
    float* out = (float*)d_out;

    __nv_bfloat16 *XQH,*XQL,*XKH,*XKL,*XVH,*XVL;
    __nv_bfloat16 *WqH,*WqL,*WkH,*WkL,*WvH,*WvL,*WoH,*WoL;
    __nv_bfloat16 *QH,*QL,*KH,*KL,*AH,*AL;
    __half *V16;
    cudaGetSymbolAddress((void**)&XQH, g_XQH); cudaGetSymbolAddress((void**)&XQL, g_XQL);
    cudaGetSymbolAddress((void**)&XKH, g_XKH); cudaGetSymbolAddress((void**)&XKL, g_XKL);
    cudaGetSymbolAddress((void**)&XVH, g_XVH); cudaGetSymbolAddress((void**)&XVL, g_XVL);
    cudaGetSymbolAddress((void**)&WqH, g_WqH); cudaGetSymbolAddress((void**)&WqL, g_WqL);
    cudaGetSymbolAddress((void**)&WkH, g_WkH); cudaGetSymbolAddress((void**)&WkL, g_WkL);
    cudaGetSymbolAddress((void**)&WvH, g_WvH); cudaGetSymbolAddress((void**)&WvL, g_WvL);
    cudaGetSymbolAddress((void**)&WoH, g_WoH); cudaGetSymbolAddress((void**)&WoL, g_WoL);
    cudaGetSymbolAddress((void**)&QH,  g_QH);  cudaGetSymbolAddress((void**)&QL,  g_QL);
    cudaGetSymbolAddress((void**)&KH,  g_KH);  cudaGetSymbolAddress((void**)&KL,  g_KL);
    cudaGetSymbolAddress((void**)&V16, g_V16);
    cudaGetSymbolAddress((void**)&AH,  g_AH);  cudaGetSymbolAddress((void**)&AL,  g_AL);

    cudaFuncSetAttribute(gemm_proj,
                         cudaFuncAttributeMaxDynamicSharedMemorySize, G_SMEM);
    cudaFuncSetAttribute(gemm_out,
                         cudaFuncAttributeMaxDynamicSharedMemorySize, G_SMEM);
    cudaFuncSetAttribute(attn_tc,
                         cudaFuncAttributeMaxDynamicSharedMemorySize, AT_SMEM);

    dim3 blk(256);
    const int nX = NELEM / 4, nW = WELEM / 4;

    SplitBatch sp;
    sp.src[0]=xQ; sp.hi[0]=XQH; sp.lo[0]=XQL; sp.n4[0]=nX;
    sp.src[1]=xK; sp.hi[1]=XKH; sp.lo[1]=XKL; sp.n4[1]=nX;
    sp.src[2]=xV; sp.hi[2]=XVH; sp.lo[2]=XVL; sp.n4[2]=nX;
    sp.src[3]=Wq; sp.hi[3]=WqH; sp.lo[3]=WqL; sp.n4[3]=nW;
    sp.src[4]=Wk; sp.hi[4]=WkH; sp.lo[4]=WkL; sp.n4[4]=nW;
    sp.src[5]=Wv; sp.hi[5]=WvH; sp.lo[5]=WvL; sp.n4[5]=nW;
    sp.src[6]=Wo; sp.hi[6]=WoH; sp.lo[6]=WoL; sp.n4[6]=nW;
    split_all<<<dim3((nX + 255) / 256, 7), blk>>>(sp);

    GemmBatch gb;
    gb.Ah[0]=XQH; gb.Al[0]=XQL; gb.Wh[0]=WqH; gb.Wl[0]=WqL; gb.bias[0]=bq;
    gb.Co[0]=QH;  gb.Cl[0]=QL;  gb.scale[0]=0.125f;
    gb.Ah[1]=XKH; gb.Al[1]=XKL; gb.Wh[1]=WkH; gb.Wl[1]=WkL; gb.bias[1]=bk;
    gb.Co[1]=KH;  gb.Cl[1]=KL;  gb.scale[1]=1.0f;
    gb.Ah[2]=XVH; gb.Al[2]=XVL; gb.Wh[2]=WvH; gb.Wl[2]=WvL; gb.bias[2]=bv;
    gb.Co[2]=V16; gb.Cl[2]=nullptr; gb.scale[2]=1.0f;
    gemm_proj<<<dim3(DD / 128, MTOT / 128, 3), blk, G_SMEM>>>(gb);

    dim3 agrid(SS / 128, HH, BB);           // (16, 16, 4)
    attn_tc<<<agrid, blk, AT_SMEM>>>(QH, QL, KH, KL, V16, AH, AL);

    gemm_out<<<dim3(DD / 128, MTOT / 128), blk, G_SMEM>>>(AH, AL, WoH, WoL, bo, out);
}

// round 14
// speedup vs baseline: 5.0377x; 1.1676x over previous
#include <cuda_runtime.h>
#include <cuda_bf16.h>
#include <cuda_fp16.h>
#include <cstdint>

// Problem constants
#define BB   4
#define SS   2048
#define DD   1024
#define HH   16
#define DKK  64
#define MTOT (BB*SS)
#define NELEM (MTOT*DD)      // 8388608
#define WELEM (DD*DD)        // 1048576

// Scratch (no cudaMalloc allowed)
__device__ __nv_bfloat16 g_XQH[NELEM], g_XQL[NELEM];
__device__ __nv_bfloat16 g_XKH[NELEM], g_XKL[NELEM];
__device__ __nv_bfloat16 g_XVH[NELEM], g_XVL[NELEM];
__device__ __nv_bfloat16 g_WqH[WELEM], g_WqL[WELEM];
__device__ __nv_bfloat16 g_WkH[WELEM], g_WkL[WELEM];
__device__ __nv_bfloat16 g_WvH[WELEM], g_WvL[WELEM];
__device__ __nv_bfloat16 g_WoH[WELEM], g_WoL[WELEM];
__device__ __half        g_Q16[NELEM];               // Q as fp16 (pre-scaled 1/8)
__device__ __half        g_K16[NELEM];               // K as fp16
__device__ __half        g_V16[NELEM];               // V as fp16
__device__ __nv_bfloat16 g_AH[NELEM], g_AL[NELEM];   // attn out, bf16 hi/lo

// ---------------------------------------------------------------------------
// Helpers
// ---------------------------------------------------------------------------
__device__ __forceinline__ uint32_t smem_u32(const void* p) {
    uint32_t a;
    asm("{ .reg .u64 t; cvta.to.shared.u64 t, %1; cvt.u32.u64 %0, t; }"
        : "=r"(a) : "l"(p));
    return a;
}

__device__ __forceinline__ void ldm_x4(uint32_t& r0, uint32_t& r1,
                                       uint32_t& r2, uint32_t& r3, uint32_t addr) {
    asm volatile("ldmatrix.sync.aligned.m8n8.x4.shared.b16 {%0,%1,%2,%3}, [%4];"
                 : "=r"(r0), "=r"(r1), "=r"(r2), "=r"(r3) : "r"(addr));
}

__device__ __forceinline__ void ldm_x4_t(uint32_t& r0, uint32_t& r1,
                                         uint32_t& r2, uint32_t& r3, uint32_t addr) {
    asm volatile("ldmatrix.sync.aligned.m8n8.x4.trans.shared.b16 {%0,%1,%2,%3}, [%4];"
                 : "=r"(r0), "=r"(r1), "=r"(r2), "=r"(r3) : "r"(addr));
}

// bf16 MMA
__device__ __forceinline__ void mma16816(float* d,
                                         uint32_t a0, uint32_t a1, uint32_t a2, uint32_t a3,
                                         uint32_t b0, uint32_t b1) {
    asm volatile(
        "mma.sync.aligned.m16n8k16.row.col.f32.bf16.bf16.f32 "
        "{%0,%1,%2,%3}, {%4,%5,%6,%7}, {%8,%9}, {%0,%1,%2,%3};"
        : "+f"(d[0]), "+f"(d[1]), "+f"(d[2]), "+f"(d[3])
        : "r"(a0), "r"(a1), "r"(a2), "r"(a3), "r"(b0), "r"(b1));
}

// fp16 MMA
__device__ __forceinline__ void mma16816h(float* d,
                                          uint32_t a0, uint32_t a1, uint32_t a2, uint32_t a3,
                                          uint32_t b0, uint32_t b1) {
    asm volatile(
        "mma.sync.aligned.m16n8k16.row.col.f32.f16.f16.f32 "
        "{%0,%1,%2,%3}, {%4,%5,%6,%7}, {%8,%9}, {%0,%1,%2,%3};"
        : "+f"(d[0]), "+f"(d[1]), "+f"(d[2]), "+f"(d[3])
        : "r"(a0), "r"(a1), "r"(a2), "r"(a3), "r"(b0), "r"(b1));
}

__device__ __forceinline__ void split2(float x0, float x1, uint32_t& h, uint32_t& l) {
    asm("cvt.rn.bf16x2.f32 %0, %1, %2;" : "=r"(h) : "f"(x1), "f"(x0));
    float h0 = __uint_as_float(h << 16);
    float h1 = __uint_as_float(h & 0xffff0000u);
    asm("cvt.rn.bf16x2.f32 %0, %1, %2;" : "=r"(l) : "f"(x1 - h1), "f"(x0 - h0));
}

__device__ __forceinline__ uint32_t packh2(float x0, float x1) {
    uint32_t r;
    asm("cvt.rn.f16x2.f32 %0, %1, %2;" : "=r"(r) : "f"(x1), "f"(x0));
    return r;
}

__device__ __forceinline__ void cp16(uint32_t s, const void* g) {
    asm volatile("cp.async.cg.shared.global [%0], [%1], 16;" :: "r"(s), "l"(g) : "memory");
}
#define CP_COMMIT() asm volatile("cp.async.commit_group;" ::: "memory")
#define CP_WAIT1()  asm volatile("cp.async.wait_group 1;" ::: "memory")
#define CP_WAIT0()  asm volatile("cp.async.wait_group 0;" ::: "memory")

// ---------------------------------------------------------------------------
// Batched elementwise fp32 -> bf16 hi/lo split: 7 tensors in one launch
// ---------------------------------------------------------------------------
struct SplitBatch {
    const float* src[7];
    __nv_bfloat16* hi[7];
    __nv_bfloat16* lo[7];
    int n4[7];
};

__global__ __launch_bounds__(256) void split_all(SplitBatch sp) {
    const int z = blockIdx.y;
    const int i = blockIdx.x * 256 + threadIdx.x;
    if (i >= sp.n4[z]) return;
    float4 v = ((const float4*)sp.src[z])[i];
    uint32_t h0, l0, h1, l1;
    split2(v.x, v.y, h0, l0);
    split2(v.z, v.w, h1, l1);
    ((uint2*)sp.hi[z])[i] = make_uint2(h0, h1);
    ((uint2*)sp.lo[z])[i] = make_uint2(l0, l1);
}

// ---------------------------------------------------------------------------
// GEMM core: 128x128 tile, BK=32, XOR-swizzled 128B rows [hi|lo],
// 3-stage cp.async, one barrier per chunk, bf16 3-product split.
// ---------------------------------------------------------------------------
#define GS_MAT   16384
#define GS_STAGE (2 * GS_MAT)
#define G_SMEM   (3 * GS_STAGE)         // 98304 B

struct GemmBatch {
    const __nv_bfloat16 *Ah[3], *Al[3], *Wh[3], *Wl[3];
    const float* bias[3];
    __half* C16[3];
    float scale[3];
};

template <typename EPI>
__device__ __forceinline__ void gemm_body(
    const __nv_bfloat16* __restrict__ Ahi, const __nv_bfloat16* __restrict__ Alo,
    const __nv_bfloat16* __restrict__ Whi, const __nv_bfloat16* __restrict__ Wlo,
    EPI epi)
{
    extern __shared__ uint16_t gsm[];
    const uint32_t sb = smem_u32(gsm);

    const int tid  = threadIdx.x;
    const int lane = tid & 31;
    const int wid  = tid >> 5;
    const int wm   = wid & 3;
    const int wn   = wid >> 2;
    const int bm   = blockIdx.y * 128;
    const int bn   = blockIdx.x * 128;

    float acc[2][8][4];
#pragma unroll
    for (int mt = 0; mt < 2; mt++)
#pragma unroll
        for (int nt = 0; nt < 8; nt++)
#pragma unroll
            for (int q = 0; q < 4; q++) acc[mt][nt][q] = 0.f;

    const int a_row = wm * 32 + (lane & 15);
    const int a_kh  = (lane >> 4) * 8;
    const int b_off = (lane & 7) + ((lane & 16) ? 8 : 0);
    const int b_kh  = (lane & 8) ? 8 : 0;
    const uint32_t xkey = (uint32_t)(lane & 7);

    auto load_chunk = [&](int ch, int s) {
        const int k0 = ch * 32;
        const uint32_t sbase = sb + (uint32_t)s * GS_STAGE;
#pragma unroll
        for (int it = 0; it < 8; it++) {
            int idx = tid + it * 256;
            int m   = idx >> 10;
            int rem = idx & 1023;
            int r   = rem >> 3;
            int c   = rem & 7;
            const __nv_bfloat16* src =
                (m == 0) ? ((c < 4) ? Ahi : Alo) : ((c < 4) ? Whi : Wlo);
            int koff = (c & 3) * 8;
            size_t g = (size_t)((m == 0 ? bm : bn) + r) * DD + k0 + koff;
            uint32_t soff = (uint32_t)(m * GS_MAT) + (uint32_t)(r * 128) +
                            (((uint32_t)c ^ ((uint32_t)r & 7u)) << 4);
            cp16(sbase + soff, src + g);
        }
    };

    load_chunk(0, 0); CP_COMMIT();
    load_chunk(1, 1); CP_COMMIT();

    for (int ch = 0; ch < 32; ch++) {
        if (ch < 31) { CP_WAIT1(); } else { CP_WAIT0(); }
        __syncthreads();
        if (ch + 2 < 32) {
            load_chunk(ch + 2, (ch + 2) % 3);
            CP_COMMIT();
        }

        const uint32_t ss = sb + (uint32_t)(ch % 3) * GS_STAGE;
        const uint32_t sA = ss;
        const uint32_t sW = ss + GS_MAT;

#pragma unroll
        for (int ks = 0; ks < 2; ks++) {
            const int kb = ks * 16;
            const uint32_t chi = (uint32_t)((kb + a_kh) >> 3);
            uint32_t ah[2][4], al[2][4];
#pragma unroll
            for (int mt = 0; mt < 2; mt++) {
                const uint32_t rb = (uint32_t)((a_row + mt * 16) * 128);
                ldm_x4(ah[mt][0], ah[mt][1], ah[mt][2], ah[mt][3],
                       sA + rb + ((chi ^ xkey) << 4));
                ldm_x4(al[mt][0], al[mt][1], al[mt][2], al[mt][3],
                       sA + rb + (((chi + 4) ^ xkey) << 4));
            }
            const uint32_t cbi = (uint32_t)((kb + b_kh) >> 3);
#pragma unroll
            for (int ng = 0; ng < 4; ng++) {
                const uint32_t rb = (uint32_t)((wn * 64 + ng * 16 + b_off) * 128);
                uint32_t bh0, bh1, bh2, bh3, bl0, bl1, bl2, bl3;
                ldm_x4(bh0, bh1, bh2, bh3, sW + rb + ((cbi ^ xkey) << 4));
                ldm_x4(bl0, bl1, bl2, bl3, sW + rb + (((cbi + 4) ^ xkey) << 4));
#pragma unroll
                for (int mt = 0; mt < 2; mt++) {
                    mma16816(acc[mt][2*ng],   ah[mt][0], ah[mt][1], ah[mt][2], ah[mt][3], bh0, bh1);
                    mma16816(acc[mt][2*ng],   ah[mt][0], ah[mt][1], ah[mt][2], ah[mt][3], bl0, bl1);
                    mma16816(acc[mt][2*ng],   al[mt][0], al[mt][1], al[mt][2], al[mt][3], bh0, bh1);
                    mma16816(acc[mt][2*ng+1], ah[mt][0], ah[mt][1], ah[mt][2], ah[mt][3], bh2, bh3);
                    mma16816(acc[mt][2*ng+1], ah[mt][0], ah[mt][1], ah[mt][2], ah[mt][3], bl2, bl3);
                    mma16816(acc[mt][2*ng+1], al[mt][0], al[mt][1], al[mt][2], al[mt][3], bh2, bh3);
                }
            }
        }
    }

#pragma unroll
    for (int mt = 0; mt < 2; mt++) {
#pragma unroll
        for (int nt = 0; nt < 8; nt++) {
            int row = bm + wm * 32 + mt * 16 + (lane >> 2);
            int col = bn + wn * 64 + nt * 8 + (lane & 3) * 2;
            epi(row, col, acc[mt][nt]);
        }
    }
}

// Projections: 3 GEMMs in one launch; ALL outputs direct fp16
// (Q pre-scaled by 1/8; fp16 rounding of Q/K/V is within error budget).
__global__ __launch_bounds__(256, 2) void gemm_proj(GemmBatch gb) {
    const int z = blockIdx.z;
    const __nv_bfloat16* Ahi = gb.Ah[z];
    const __nv_bfloat16* Alo = gb.Al[z];
    const __nv_bfloat16* Whi = gb.Wh[z];
    const __nv_bfloat16* Wlo = gb.Wl[z];
    const float* bias = gb.bias[z];
    __half* C16 = gb.C16[z];
    const float scale = gb.scale[z];

    gemm_body(Ahi, Alo, Whi, Wlo,
        [&](int row, int col, const float* a) {
            float b0 = bias[col], b1 = bias[col + 1];
            *(uint32_t*)(C16 + (size_t)row * DD + col) =
                packh2((a[0] + b0) * scale, (a[1] + b1) * scale);
            *(uint32_t*)(C16 + (size_t)(row + 8) * DD + col) =
                packh2((a[2] + b0) * scale, (a[3] + b1) * scale);
        });
}

// Final GEMM: fp32 output.
__global__ __launch_bounds__(256, 2) void gemm_out(
    const __nv_bfloat16* __restrict__ Ahi, const __nv_bfloat16* __restrict__ Alo,
    const __nv_bfloat16* __restrict__ Whi, const __nv_bfloat16* __restrict__ Wlo,
    const float* __restrict__ bias, float* __restrict__ Cf)
{
    gemm_body(Ahi, Alo, Whi, Wlo,
        [&](int row, int col, const float* a) {
            float b0 = bias[col], b1 = bias[col + 1];
            *(float2*)(Cf + (size_t)row * DD + col) = make_float2(a[0] + b0, a[1] + b1);
            *(float2*)(Cf + (size_t)(row + 8) * DD + col) = make_float2(a[2] + b0, a[3] + b1);
        });
}

// ---------------------------------------------------------------------------
// Flash attention, all-fp16 MMA operands.
// QK^T: direct fp16 (1 product, score err ~4e-4 abs).
// PV:   direct fp16 (1 product, err ~2.6e-4).
// KV stage = {K16, V16}; Q resident fp16.  cp.async 2-stage.
// Output AO as bf16 hi/lo (keeps final-GEMM error negligible).
// ---------------------------------------------------------------------------
#define AST  72
#define AQ16 0
#define AKV0 (128 * AST)
#define TKV  (64 * AST)
#define SKV  (2 * TKV)
#define AT_SMEM ((AKV0 + 2 * SKV) * 2)  // 55296 bytes

__global__ __launch_bounds__(256, 2) void attn_tc(
    const __half* __restrict__ Q16,
    const __half* __restrict__ K16,
    const __half* __restrict__ V16,
    __nv_bfloat16* __restrict__ Ohi, __nv_bfloat16* __restrict__ Olo)
{
    extern __shared__ uint16_t sm16[];
    const uint32_t sb = smem_u32(sm16);

    const int qt = blockIdx.x;
    const int h  = blockIdx.y;
    const int b  = blockIdx.z;

    const int tid  = threadIdx.x;
    const int lane = tid & 31;
    const int wid  = tid >> 5;
    const int m0   = wid * 16;

    const size_t base = ((size_t)b * SS) * DD + (size_t)h * DKK;

    // Load Q tile 128x64 fp16
    {
        const size_t qb = base + (size_t)(qt * 128) * DD;
#pragma unroll
        for (int it = 0; it < 4; it++) {
            int idx = tid + it * 256;          // 0..1023 16B-chunks
            int r   = idx >> 3;
            int c   = idx & 7;
            size_t g = qb + (size_t)r * DD + c * 8;
            uint32_t soff = (uint32_t)(r * AST + c * 8) * 2;
            *(uint4*)((char*)sm16 + AQ16 * 2 + soff) = *(const uint4*)(Q16 + g);
        }
    }

    auto load_kv = [&](int kt, int s) {
        const size_t kb = base + (size_t)(kt * 64) * DD;
        const uint32_t sbase = sb + (uint32_t)(AKV0 + s * SKV) * 2;
#pragma unroll
        for (int it = 0; it < 2; it++) {
            int idx = tid + it * 256;          // 0..511
            int r   = idx >> 3;
            int c   = idx & 7;
            size_t g = kb + (size_t)r * DD + c * 8;
            uint32_t soff = (uint32_t)(r * AST + c * 8) * 2;
            cp16(sbase + 0 * TKV * 2 + soff, K16 + g);
            cp16(sbase + 1 * TKV * 2 + soff, V16 + g);
        }
    };

    float o[8][4];
#pragma unroll
    for (int nt = 0; nt < 8; nt++)
#pragma unroll
        for (int q = 0; q < 4; q++) o[nt][q] = 0.f;
    float m0r = -1e30f, m1r = -1e30f, l0r = 0.f, l1r = 0.f;

    const int a_row = m0 + (lane & 15);
    const int a_kh  = (lane >> 4) * 8;
    const int b_off = (lane & 7) + ((lane & 16) ? 8 : 0);
    const int b_kh  = (lane & 8) ? 8 : 0;
    const int v_row = (lane & 15);
    const int v_kh  = (lane & 16) ? 8 : 0;

    load_kv(0, 0);
    CP_COMMIT();

    for (int kt = 0; kt < SS / 64; kt++) {
        if (kt < SS / 64 - 1) {
            load_kv(kt + 1, (kt + 1) & 1);
            CP_COMMIT();
            CP_WAIT1();
        } else {
            CP_WAIT0();
        }
        __syncthreads();

        const uint32_t skv = sb + (uint32_t)(AKV0 + (kt & 1) * SKV) * 2;
        const uint32_t sK = skv;
        const uint32_t sV = skv + 1 * TKV * 2;

        // S = Q K^T  (fp16, single product)
        float s[8][4];
#pragma unroll
        for (int nt = 0; nt < 8; nt++)
#pragma unroll
            for (int q = 0; q < 4; q++) s[nt][q] = 0.f;

#pragma unroll
        for (int ks = 0; ks < 4; ks++) {
            const int kb2 = ks * 16;
            uint32_t q0, q1, q2, q3;
            uint32_t qoff = (uint32_t)(a_row * AST + kb2 + a_kh) * 2;
            ldm_x4(q0, q1, q2, q3, sb + AQ16 * 2 + qoff);
#pragma unroll
            for (int ng = 0; ng < 4; ng++) {
                uint32_t koff = (uint32_t)((ng * 16 + b_off) * AST + kb2 + b_kh) * 2;
                uint32_t k0, k1, k2, k3;
                ldm_x4(k0, k1, k2, k3, sK + koff);
                mma16816h(s[2*ng],   q0, q1, q2, q3, k0, k1);
                mma16816h(s[2*ng+1], q0, q1, q2, q3, k2, k3);
            }
        }

        // Online softmax in C-fragments
        float mx0 = -1e30f, mx1 = -1e30f;
#pragma unroll
        for (int nt = 0; nt < 8; nt++) {
            mx0 = fmaxf(mx0, fmaxf(s[nt][0], s[nt][1]));
            mx1 = fmaxf(mx1, fmaxf(s[nt][2], s[nt][3]));
        }
#pragma unroll
        for (int off = 1; off <= 2; off <<= 1) {
            mx0 = fmaxf(mx0, __shfl_xor_sync(0xffffffffu, mx0, off));
            mx1 = fmaxf(mx1, __shfl_xor_sync(0xffffffffu, mx1, off));
        }
        float mn0 = fmaxf(m0r, mx0), mn1 = fmaxf(m1r, mx1);
        float al0 = __expf(m0r - mn0), al1 = __expf(m1r - mn1);
        m0r = mn0; m1r = mn1;

        float sum0 = 0.f, sum1 = 0.f;
#pragma unroll
        for (int nt = 0; nt < 8; nt++) {
            s[nt][0] = __expf(s[nt][0] - mn0);
            s[nt][1] = __expf(s[nt][1] - mn0);
            s[nt][2] = __expf(s[nt][2] - mn1);
            s[nt][3] = __expf(s[nt][3] - mn1);
            sum0 += s[nt][0] + s[nt][1];
            sum1 += s[nt][2] + s[nt][3];
        }
#pragma unroll
        for (int off = 1; off <= 2; off <<= 1) {
            sum0 += __shfl_xor_sync(0xffffffffu, sum0, off);
            sum1 += __shfl_xor_sync(0xffffffffu, sum1, off);
        }
        l0r = l0r * al0 + sum0;
        l1r = l1r * al1 + sum1;
#pragma unroll
        for (int nt = 0; nt < 8; nt++) {
            o[nt][0] *= al0; o[nt][1] *= al0;
            o[nt][2] *= al1; o[nt][3] *= al1;
        }

        // O += P V  (fp16, single product)
#pragma unroll
        for (int ksj = 0; ksj < 4; ksj++) {
            uint32_t pa0 = packh2(s[2*ksj][0],   s[2*ksj][1]);
            uint32_t pa1 = packh2(s[2*ksj][2],   s[2*ksj][3]);
            uint32_t pa2 = packh2(s[2*ksj+1][0], s[2*ksj+1][1]);
            uint32_t pa3 = packh2(s[2*ksj+1][2], s[2*ksj+1][3]);
#pragma unroll
            for (int ng = 0; ng < 4; ng++) {
                uint32_t voff = (uint32_t)((ksj * 16 + v_row) * AST + ng * 16 + v_kh) * 2;
                uint32_t v0, v1, v2, v3;
                ldm_x4_t(v0, v1, v2, v3, sV + voff);
                mma16816h(o[2*ng],   pa0, pa1, pa2, pa3, v0, v1);
                mma16816h(o[2*ng+1], pa0, pa1, pa2, pa3, v2, v3);
            }
        }
        __syncthreads();
    }

    // Normalize + store as bf16 hi/lo
    float inv0 = 1.f / l0r, inv1 = 1.f / l1r;
    const int row0 = qt * 128 + m0 + (lane >> 2);
#pragma unroll
    for (int nt = 0; nt < 8; nt++) {
        int col = nt * 8 + (lane & 3) * 2;
        uint32_t h2, l2;
        split2(o[nt][0] * inv0, o[nt][1] * inv0, h2, l2);
        *(uint32_t*)(Ohi + base + (size_t)row0 * DD + col) = h2;
        *(uint32_t*)(Olo + base + (size_t)row0 * DD + col) = l2;
        split2(o[nt][2] * inv1, o[nt][3] * inv1, h2, l2);
        *(uint32_t*)(Ohi + base + (size_t)(row0 + 8) * DD + col) = h2;
        *(uint32_t*)(Olo + base + (size_t)(row0 + 8) * DD + col) = l2;
    }
}

// ---------------------------------------------------------------------------
// Launch
// ---------------------------------------------------------------------------
extern "C" void kernel_launch(void* const* d_in, const int* in_sizes, int n_in,
                              void* d_out, int out_size)
{
    const float* xQ = (const float*)d_in[0];
    const float* xK = (const float*)d_in[1];
    const float* xV = (const float*)d_in[2];
    const float* Wq = (const float*)d_in[3];
    const float* bq = (const float*)d_in[4];
    const float* Wk = (const float*)d_in[5];
    const float* bk = (const float*)d_in[6];
    const float* Wv = (const float*)d_in[7];
    const float* bv = (const float*)d_in[8];
    const float* Wo = (const float*)d_in[9];
    const float* bo = (const float*)d_in[10];
    float* out = (float*)d_out;

    __nv_bfloat16 *XQH,*XQL,*XKH,*XKL,*XVH,*XVL;
    __nv_bfloat16 *WqH,*WqL,*WkH,*WkL,*WvH,*WvL,*WoH,*WoL;
    __nv_bfloat16 *AH,*AL;
    __half *Q16,*K16,*V16;
    cudaGetSymbolAddress((void**)&XQH, g_XQH); cudaGetSymbolAddress((void**)&XQL, g_XQL);
    cudaGetSymbolAddress((void**)&XKH, g_XKH); cudaGetSymbolAddress((void**)&XKL, g_XKL);
    cudaGetSymbolAddress((void**)&XVH, g_XVH); cudaGetSymbolAddress((void**)&XVL, g_XVL);
    cudaGetSymbolAddress((void**)&WqH, g_WqH); cudaGetSymbolAddress((void**)&WqL, g_WqL);
    cudaGetSymbolAddress((void**)&WkH, g_WkH); cudaGetSymbolAddress((void**)&WkL, g_WkL);
    cudaGetSymbolAddress((void**)&WvH, g_WvH); cudaGetSymbolAddress((void**)&WvL, g_WvL);
    cudaGetSymbolAddress((void**)&WoH, g_WoH); cudaGetSymbolAddress((void**)&WoL, g_WoL);
    cudaGetSymbolAddress((void**)&Q16, g_Q16);
    cudaGetSymbolAddress((void**)&K16, g_K16);
    cudaGetSymbolAddress((void**)&V16, g_V16);
    cudaGetSymbolAddress((void**)&AH,  g_AH);  cudaGetSymbolAddress((void**)&AL,  g_AL);

    cudaFuncSetAttribute(gemm_proj,
                         cudaFuncAttributeMaxDynamicSharedMemorySize, G_SMEM);
    cudaFuncSetAttribute(gemm_out,
                         cudaFuncAttributeMaxDynamicSharedMemorySize, G_SMEM);
    cudaFuncSetAttribute(attn_tc,
                         cudaFuncAttributeMaxDynamicSharedMemorySize, AT_SMEM);

    dim3 blk(256);
    const int nX = NELEM / 4, nW = WELEM / 4;

    SplitBatch sp;
    sp.src[0]=xQ; sp.hi[0]=XQH; sp.lo[0]=XQL; sp.n4[0]=nX;
    sp.src[1]=xK; sp.hi[1]=XKH; sp.lo[1]=XKL; sp.n4[1]=nX;
    sp.src[2]=xV; sp.hi[2]=XVH; sp.lo[2]=XVL; sp.n4[2]=nX;
    sp.src[3]=Wq; sp.hi[3]=WqH; sp.lo[3]=WqL; sp.n4[3]=nW;
    sp.src[4]=Wk; sp.hi[4]=WkH; sp.lo[4]=WkL; sp.n4[4]=nW;
    sp.src[5]=Wv; sp.hi[5]=WvH; sp.lo[5]=WvL; sp.n4[5]=nW;
    sp.src[6]=Wo; sp.hi[6]=WoH; sp.lo[6]=WoL; sp.n4[6]=nW;
    split_all<<<dim3((nX + 255) / 256, 7), blk>>>(sp);

    GemmBatch gb;
    gb.Ah[0]=XQH; gb.Al[0]=XQL; gb.Wh[0]=WqH; gb.Wl[0]=WqL; gb.bias[0]=bq;
    gb.C16[0]=Q16; gb.scale[0]=0.125f;
    gb.Ah[1]=XKH; gb.Al[1]=XKL; gb.Wh[1]=WkH; gb.Wl[1]=WkL; gb.bias[1]=bk;
    gb.C16[1]=K16; gb.scale[1]=1.0f;
    gb.Ah[2]=XVH; gb.Al[2]=XVL; gb.Wh[2]=WvH; gb.Wl[2]=WvL; gb.bias[2]=bv;
    gb.C16[2]=V16; gb.scale[2]=1.0f;
    gemm_proj<<<dim3(DD / 128, MTOT / 128, 3), blk, G_SMEM>>>(gb);

    dim3 agrid(SS / 128, HH, BB);           // (16, 16, 4)
    attn_tc<<<agrid, blk, AT_SMEM>>>(Q16, K16, V16, AH, AL);

    gemm_out<<<dim3(DD / 128, MTOT / 128), blk, G_SMEM>>>(AH, AL, WoH, WoL, bo, out);
}

// round 16
// speedup vs baseline: 6.3985x; 1.2701x over previous
#include <cuda_runtime.h>
#include <cuda_bf16.h>
#include <cuda_fp16.h>
#include <cstdint>

// Problem constants
#define BB   4
#define SS   2048
#define DD   1024
#define HH   16
#define DKK  64
#define MTOT (BB*SS)
#define NELEM (MTOT*DD)      // 8388608
#define WELEM (DD*DD)        // 1048576

// Scratch (no cudaMalloc allowed)
__device__ __half g_XH16[3 * NELEM];   // x inputs split: fp16 hi
__device__ __half g_XL16[3 * NELEM];   // fp16 lo (residual)
__device__ __half g_W16 [4 * WELEM];   // Wq,Wk,Wv,Wo direct fp16
__device__ __half g_Q16[NELEM];        // Q fp16 (pre-scaled 1/8)
__device__ __half g_K16[NELEM];
__device__ __half g_V16[NELEM];
__device__ __half g_AH16[NELEM];       // attn out fp16 hi
__device__ __half g_AL16[NELEM];       // attn out fp16 lo

// ---------------------------------------------------------------------------
// Helpers
// ---------------------------------------------------------------------------
__device__ __forceinline__ uint32_t smem_u32(const void* p) {
    uint32_t a;
    asm("{ .reg .u64 t; cvta.to.shared.u64 t, %1; cvt.u32.u64 %0, t; }"
        : "=r"(a) : "l"(p));
    return a;
}

__device__ __forceinline__ void ldm_x4(uint32_t& r0, uint32_t& r1,
                                       uint32_t& r2, uint32_t& r3, uint32_t addr) {
    asm volatile("ldmatrix.sync.aligned.m8n8.x4.shared.b16 {%0,%1,%2,%3}, [%4];"
                 : "=r"(r0), "=r"(r1), "=r"(r2), "=r"(r3) : "r"(addr));
}

__device__ __forceinline__ void ldm_x4_t(uint32_t& r0, uint32_t& r1,
                                         uint32_t& r2, uint32_t& r3, uint32_t addr) {
    asm volatile("ldmatrix.sync.aligned.m8n8.x4.trans.shared.b16 {%0,%1,%2,%3}, [%4];"
                 : "=r"(r0), "=r"(r1), "=r"(r2), "=r"(r3) : "r"(addr));
}

// fp16 MMA, fp32 accumulate
__device__ __forceinline__ void mma16816h(float* d,
                                          uint32_t a0, uint32_t a1, uint32_t a2, uint32_t a3,
                                          uint32_t b0, uint32_t b1) {
    asm volatile(
        "mma.sync.aligned.m16n8k16.row.col.f32.f16.f16.f32 "
        "{%0,%1,%2,%3}, {%4,%5,%6,%7}, {%8,%9}, {%0,%1,%2,%3};"
        : "+f"(d[0]), "+f"(d[1]), "+f"(d[2]), "+f"(d[3])
        : "r"(a0), "r"(a1), "r"(a2), "r"(a3), "r"(b0), "r"(b1));
}

__device__ __forceinline__ uint32_t packh2(float x0, float x1) {
    uint32_t r;
    asm("cvt.rn.f16x2.f32 %0, %1, %2;" : "=r"(r) : "f"(x1), "f"(x0));
    return r;
}

// fp32 pair -> fp16x2 hi + fp16x2 lo (exact to ~eps^2)
__device__ __forceinline__ void splith2(float x0, float x1, uint32_t& h, uint32_t& l) {
    __half h0 = __float2half_rn(x0), h1 = __float2half_rn(x1);
    float r0 = x0 - __half2float(h0);
    float r1 = x1 - __half2float(h1);
    h = ((uint32_t)__half_as_ushort(h1) << 16) | (uint32_t)__half_as_ushort(h0);
    l = packh2(r0, r1);
}

__device__ __forceinline__ void cp16(uint32_t s, const void* g) {
    asm volatile("cp.async.cg.shared.global [%0], [%1], 16;" :: "r"(s), "l"(g) : "memory");
}
#define CP_COMMIT() asm volatile("cp.async.commit_group;" ::: "memory")
#define CP_WAIT1()  asm volatile("cp.async.wait_group 1;" ::: "memory")
#define CP_WAIT0()  asm volatile("cp.async.wait_group 0;" ::: "memory")

// ---------------------------------------------------------------------------
// Batched preprocessing: z 0..2 -> split x into fp16 hi/lo; z 3..6 -> W fp16.
// ---------------------------------------------------------------------------
struct SplitBatch {
    const float* src[7];
    __half* hi[7];
    __half* lo[7];     // null for convert-only
    int n4[7];
    int mode[7];       // 0 split, 1 convert
};

__global__ __launch_bounds__(256) void split_all(SplitBatch sp) {
    const int z = blockIdx.y;
    const int i = blockIdx.x * 256 + threadIdx.x;
    if (i >= sp.n4[z]) return;
    float4 v = ((const float4*)sp.src[z])[i];
    if (sp.mode[z]) {
        ((uint2*)sp.hi[z])[i] = make_uint2(packh2(v.x, v.y), packh2(v.z, v.w));
    } else {
        uint32_t h0, l0, h1, l1;
        splith2(v.x, v.y, h0, l0);
        splith2(v.z, v.w, h1, l1);
        ((uint2*)sp.hi[z])[i] = make_uint2(h0, h1);
        ((uint2*)sp.lo[z])[i] = make_uint2(l0, l1);
    }
}

// ---------------------------------------------------------------------------
// GEMM core: C[8192,1024] = (Ahi+Alo) @ W16^T + bias, all fp16 operands.
// 2 MMA products (Ahi*W + Alo*W); A exact to eps^2, W carries fp16 rounding.
// CTA tile 128x128, BK=64, XOR-swizzled 128B rows (8x16B chunks, c^(r&7)).
// 2-stage cp.async, one barrier per chunk (16 chunks).
// 8 warps = 4(m) x 2(n); warp tile 32x64.
// ---------------------------------------------------------------------------
#define GS_MAT   16384                  // 128 rows x 128B (64 fp16 k-vals)
#define GS_STAGE (3 * GS_MAT)           // Ahi + Alo + W = 49152 B
#define G_SMEM   (2 * GS_STAGE)         // 98304 B -> 2 CTAs/SM

struct GemmBatch {
    const __half *Ah[3], *Al[3], *W[3];
    const float* bias[3];
    __half* C16[3];
    float scale[3];
};

template <typename EPI>
__device__ __forceinline__ void gemm_body(
    const __half* __restrict__ Ahi, const __half* __restrict__ Alo,
    const __half* __restrict__ W16, EPI epi)
{
    extern __shared__ uint16_t gsm[];
    const uint32_t sb = smem_u32(gsm);

    const int tid  = threadIdx.x;
    const int lane = tid & 31;
    const int wid  = tid >> 5;
    const int wm   = wid & 3;
    const int wn   = wid >> 2;
    const int bm   = blockIdx.y * 128;
    const int bn   = blockIdx.x * 128;

    float acc[2][8][4];
#pragma unroll
    for (int mt = 0; mt < 2; mt++)
#pragma unroll
        for (int nt = 0; nt < 8; nt++)
#pragma unroll
            for (int q = 0; q < 4; q++) acc[mt][nt][q] = 0.f;

    const int a_row = wm * 32 + (lane & 15);
    const int a_kc  = (lane >> 4);             // 0 or 1 (k-half chunk)
    const int b_off = (lane & 7) + ((lane & 16) ? 8 : 0);
    const int b_kc  = (lane & 8) ? 1 : 0;
    const uint32_t xkey = (uint32_t)(lane & 7);

    // Load one BK=64 chunk (3 mats x 128 rows x 8 chunks = 3072 cp16)
    auto load_chunk = [&](int ch, int s) {
        const int k0 = ch * 64;
        const uint32_t sbase = sb + (uint32_t)s * GS_STAGE;
#pragma unroll
        for (int it = 0; it < 12; it++) {
            int idx = tid + it * 256;          // 0..3071
            int m   = idx >> 10;               // 0 Ahi, 1 Alo, 2 W
            int rem = idx & 1023;
            int r   = rem >> 3;                // row 0..127
            int c   = rem & 7;                 // chunk 0..7
            const __half* src = (m == 0) ? Ahi : (m == 1) ? Alo : W16;
            int rowg = (m == 2 ? bn : bm) + r;
            size_t g = (size_t)rowg * DD + k0 + c * 8;
            uint32_t soff = (uint32_t)(m * GS_MAT) + (uint32_t)(r * 128) +
                            (((uint32_t)c ^ ((uint32_t)r & 7u)) << 4);
            cp16(sbase + soff, src + g);
        }
    };

    load_chunk(0, 0); CP_COMMIT();

    for (int ch = 0; ch < 16; ch++) {
        CP_WAIT0();
        __syncthreads();
        if (ch + 1 < 16) {
            load_chunk(ch + 1, (ch + 1) & 1);
            CP_COMMIT();
        }

        const uint32_t ss  = sb + (uint32_t)(ch & 1) * GS_STAGE;
        const uint32_t sAh = ss;
        const uint32_t sAl = ss + GS_MAT;
        const uint32_t sW  = ss + 2 * GS_MAT;

#pragma unroll
        for (int ks = 0; ks < 4; ks++) {
            const uint32_t chiA = (uint32_t)(ks * 2 + a_kc);
            uint32_t ah[2][4], al[2][4];
#pragma unroll
            for (int mt = 0; mt < 2; mt++) {
                const uint32_t rb = (uint32_t)((a_row + mt * 16) * 128);
                ldm_x4(ah[mt][0], ah[mt][1], ah[mt][2], ah[mt][3],
                       sAh + rb + ((chiA ^ xkey) << 4));
                ldm_x4(al[mt][0], al[mt][1], al[mt][2], al[mt][3],
                       sAl + rb + ((chiA ^ xkey) << 4));
            }
            const uint32_t cbi = (uint32_t)(ks * 2 + b_kc);
#pragma unroll
            for (int ng = 0; ng < 4; ng++) {
                const uint32_t rb = (uint32_t)((wn * 64 + ng * 16 + b_off) * 128);
                uint32_t w0, w1, w2, w3;
                ldm_x4(w0, w1, w2, w3, sW + rb + ((cbi ^ xkey) << 4));
#pragma unroll
                for (int mt = 0; mt < 2; mt++) {
                    mma16816h(acc[mt][2*ng],   ah[mt][0], ah[mt][1], ah[mt][2], ah[mt][3], w0, w1);
                    mma16816h(acc[mt][2*ng],   al[mt][0], al[mt][1], al[mt][2], al[mt][3], w0, w1);
                    mma16816h(acc[mt][2*ng+1], ah[mt][0], ah[mt][1], ah[mt][2], ah[mt][3], w2, w3);
                    mma16816h(acc[mt][2*ng+1], al[mt][0], al[mt][1], al[mt][2], al[mt][3], w2, w3);
                }
            }
        }
    }

#pragma unroll
    for (int mt = 0; mt < 2; mt++) {
#pragma unroll
        for (int nt = 0; nt < 8; nt++) {
            int row = bm + wm * 32 + mt * 16 + (lane >> 2);
            int col = bn + wn * 64 + nt * 8 + (lane & 3) * 2;
            epi(row, col, acc[mt][nt]);
        }
    }
}

// Projections: 3 GEMMs in one launch, fp16 output (Q pre-scaled 1/8).
__global__ __launch_bounds__(256, 2) void gemm_proj(GemmBatch gb) {
    const int z = blockIdx.z;
    const __half* Ahi = gb.Ah[z];
    const __half* Alo = gb.Al[z];
    const __half* W16 = gb.W[z];
    const float* bias = gb.bias[z];
    __half* C16 = gb.C16[z];
    const float scale = gb.scale[z];

    gemm_body(Ahi, Alo, W16,
        [&](int row, int col, const float* a) {
            float b0 = bias[col], b1 = bias[col + 1];
            *(uint32_t*)(C16 + (size_t)row * DD + col) =
                packh2((a[0] + b0) * scale, (a[1] + b1) * scale);
            *(uint32_t*)(C16 + (size_t)(row + 8) * DD + col) =
                packh2((a[2] + b0) * scale, (a[3] + b1) * scale);
        });
}

// Final GEMM: fp32 output.
__global__ __launch_bounds__(256, 2) void gemm_out(
    const __half* __restrict__ Ahi, const __half* __restrict__ Alo,
    const __half* __restrict__ W16,
    const float* __restrict__ bias, float* __restrict__ Cf)
{
    gemm_body(Ahi, Alo, W16,
        [&](int row, int col, const float* a) {
            float b0 = bias[col], b1 = bias[col + 1];
            *(float2*)(Cf + (size_t)row * DD + col) = make_float2(a[0] + b0, a[1] + b1);
            *(float2*)(Cf + (size_t)(row + 8) * DD + col) = make_float2(a[2] + b0, a[3] + b1);
        });
}

// ---------------------------------------------------------------------------
// Flash attention, all-fp16 MMA operands (unchanged math from round 14);
// epilogue now emits AO as fp16 hi/lo for the 2-product final GEMM.
// ---------------------------------------------------------------------------
#define AST  72
#define AQ16 0
#define AKV0 (128 * AST)
#define TKV  (64 * AST)
#define SKV  (2 * TKV)
#define AT_SMEM ((AKV0 + 2 * SKV) * 2)  // 55296 bytes

__global__ __launch_bounds__(256, 2) void attn_tc(
    const __half* __restrict__ Q16,
    const __half* __restrict__ K16,
    const __half* __restrict__ V16,
    __half* __restrict__ Ohi, __half* __restrict__ Olo)
{
    extern __shared__ uint16_t sm16[];
    const uint32_t sb = smem_u32(sm16);

    const int qt = blockIdx.x;
    const int h  = blockIdx.y;
    const int b  = blockIdx.z;

    const int tid  = threadIdx.x;
    const int lane = tid & 31;
    const int wid  = tid >> 5;
    const int m0   = wid * 16;

    const size_t base = ((size_t)b * SS) * DD + (size_t)h * DKK;

    // Load Q tile 128x64 fp16
    {
        const size_t qb = base + (size_t)(qt * 128) * DD;
#pragma unroll
        for (int it = 0; it < 4; it++) {
            int idx = tid + it * 256;
            int r   = idx >> 3;
            int c   = idx & 7;
            size_t g = qb + (size_t)r * DD + c * 8;
            uint32_t soff = (uint32_t)(r * AST + c * 8) * 2;
            *(uint4*)((char*)sm16 + AQ16 * 2 + soff) = *(const uint4*)(Q16 + g);
        }
    }

    auto load_kv = [&](int kt, int s) {
        const size_t kb = base + (size_t)(kt * 64) * DD;
        const uint32_t sbase = sb + (uint32_t)(AKV0 + s * SKV) * 2;
#pragma unroll
        for (int it = 0; it < 2; it++) {
            int idx = tid + it * 256;
            int r   = idx >> 3;
            int c   = idx & 7;
            size_t g = kb + (size_t)r * DD + c * 8;
            uint32_t soff = (uint32_t)(r * AST + c * 8) * 2;
            cp16(sbase + 0 * TKV * 2 + soff, K16 + g);
            cp16(sbase + 1 * TKV * 2 + soff, V16 + g);
        }
    };

    float o[8][4];
#pragma unroll
    for (int nt = 0; nt < 8; nt++)
#pragma unroll
        for (int q = 0; q < 4; q++) o[nt][q] = 0.f;
    float m0r = -1e30f, m1r = -1e30f, l0r = 0.f, l1r = 0.f;

    const int a_row = m0 + (lane & 15);
    const int a_kh  = (lane >> 4) * 8;
    const int b_off = (lane & 7) + ((lane & 16) ? 8 : 0);
    const int b_kh  = (lane & 8) ? 8 : 0;
    const int v_row = (lane & 15);
    const int v_kh  = (lane & 16) ? 8 : 0;

    load_kv(0, 0);
    CP_COMMIT();

    for (int kt = 0; kt < SS / 64; kt++) {
        if (kt < SS / 64 - 1) {
            load_kv(kt + 1, (kt + 1) & 1);
            CP_COMMIT();
            CP_WAIT1();
        } else {
            CP_WAIT0();
        }
        __syncthreads();

        const uint32_t skv = sb + (uint32_t)(AKV0 + (kt & 1) * SKV) * 2;
        const uint32_t sK = skv;
        const uint32_t sV = skv + 1 * TKV * 2;

        // S = Q K^T  (fp16, single product)
        float s[8][4];
#pragma unroll
        for (int nt = 0; nt < 8; nt++)
#pragma unroll
            for (int q = 0; q < 4; q++) s[nt][q] = 0.f;

#pragma unroll
        for (int ks = 0; ks < 4; ks++) {
            const int kb2 = ks * 16;
            uint32_t q0, q1, q2, q3;
            uint32_t qoff = (uint32_t)(a_row * AST + kb2 + a_kh) * 2;
            ldm_x4(q0, q1, q2, q3, sb + AQ16 * 2 + qoff);
#pragma unroll
            for (int ng = 0; ng < 4; ng++) {
                uint32_t koff = (uint32_t)((ng * 16 + b_off) * AST + kb2 + b_kh) * 2;
                uint32_t k0, k1, k2, k3;
                ldm_x4(k0, k1, k2, k3, sK + koff);
                mma16816h(s[2*ng],   q0, q1, q2, q3, k0, k1);
                mma16816h(s[2*ng+1], q0, q1, q2, q3, k2, k3);
            }
        }

        // Online softmax in C-fragments
        float mx0 = -1e30f, mx1 = -1e30f;
#pragma unroll
        for (int nt = 0; nt < 8; nt++) {
            mx0 = fmaxf(mx0, fmaxf(s[nt][0], s[nt][1]));
            mx1 = fmaxf(mx1, fmaxf(s[nt][2], s[nt][3]));
        }
#pragma unroll
        for (int off = 1; off <= 2; off <<= 1) {
            mx0 = fmaxf(mx0, __shfl_xor_sync(0xffffffffu, mx0, off));
            mx1 = fmaxf(mx1, __shfl_xor_sync(0xffffffffu, mx1, off));
        }
        float mn0 = fmaxf(m0r, mx0), mn1 = fmaxf(m1r, mx1);
        float al0 = __expf(m0r - mn0), al1 = __expf(m1r - mn1);
        m0r = mn0; m1r = mn1;

        float sum0 = 0.f, sum1 = 0.f;
#pragma unroll
        for (int nt = 0; nt < 8; nt++) {
            s[nt][0] = __expf(s[nt][0] - mn0);
            s[nt][1] = __expf(s[nt][1] - mn0);
            s[nt][2] = __expf(s[nt][2] - mn1);
            s[nt][3] = __expf(s[nt][3] - mn1);
            sum0 += s[nt][0] + s[nt][1];
            sum1 += s[nt][2] + s[nt][3];
        }
#pragma unroll
        for (int off = 1; off <= 2; off <<= 1) {
            sum0 += __shfl_xor_sync(0xffffffffu, sum0, off);
            sum1 += __shfl_xor_sync(0xffffffffu, sum1, off);
        }
        l0r = l0r * al0 + sum0;
        l1r = l1r * al1 + sum1;
#pragma unroll
        for (int nt = 0; nt < 8; nt++) {
            o[nt][0] *= al0; o[nt][1] *= al0;
            o[nt][2] *= al1; o[nt][3] *= al1;
        }

        // O += P V  (fp16, single product)
#pragma unroll
        for (int ksj = 0; ksj < 4; ksj++) {
            uint32_t pa0 = packh2(s[2*ksj][0],   s[2*ksj][1]);
            uint32_t pa1 = packh2(s[2*ksj][2],   s[2*ksj][3]);
            uint32_t pa2 = packh2(s[2*ksj+1][0], s[2*ksj+1][1]);
            uint32_t pa3 = packh2(s[2*ksj+1][2], s[2*ksj+1][3]);
#pragma unroll
            for (int ng = 0; ng < 4; ng++) {
                uint32_t voff = (uint32_t)((ksj * 16 + v_row) * AST + ng * 16 + v_kh) * 2;
                uint32_t v0, v1, v2, v3;
                ldm_x4_t(v0, v1, v2, v3, sV + voff);
                mma16816h(o[2*ng],   pa0, pa1, pa2, pa3, v0, v1);
                mma16816h(o[2*ng+1], pa0, pa1, pa2, pa3, v2, v3);
            }
        }
        __syncthreads();
    }

    // Normalize + store as fp16 hi/lo (exact to eps^2 for the final GEMM)
    float inv0 = 1.f / l0r, inv1 = 1.f / l1r;
    const int row0 = qt * 128 + m0 + (lane >> 2);
#pragma unroll
    for (int nt = 0; nt < 8; nt++) {
        int col = nt * 8 + (lane & 3) * 2;
        uint32_t h2, l2;
        splith2(o[nt][0] * inv0, o[nt][1] * inv0, h2, l2);
        *(uint32_t*)(Ohi + base + (size_t)row0 * DD + col) = h2;
        *(uint32_t*)(Olo + base + (size_t)row0 * DD + col) = l2;
        splith2(o[nt][2] * inv1, o[nt][3] * inv1, h2, l2);
        *(uint32_t*)(Ohi + base + (size_t)(row0 + 8) * DD + col) = h2;
        *(uint32_t*)(Olo + base + (size_t)(row0 + 8) * DD + col) = l2;
    }
}

// ---------------------------------------------------------------------------
// Launch
// ---------------------------------------------------------------------------
extern "C" void kernel_launch(void* const* d_in, const int* in_sizes, int n_in,
                              void* d_out, int out_size)
{
    const float* xQ = (const float*)d_in[0];
    const float* xK = (const float*)d_in[1];
    const float* xV = (const float*)d_in[2];
    const float* Wq = (const float*)d_in[3];
    const float* bq = (const float*)d_in[4];
    const float* Wk = (const float*)d_in[5];
    const float* bk = (const float*)d_in[6];
    const float* Wv = (const float*)d_in[7];
    const float* bv = (const float*)d_in[8];
    const float* Wo = (const float*)d_in[9];
    const float* bo = (const float*)d_in[10];
    float* out = (float*)d_out;

    __half *XH16, *XL16, *W16, *Q16, *K16, *V16, *AH16, *AL16;
    cudaGetSymbolAddress((void**)&XH16, g_XH16);
    cudaGetSymbolAddress((void**)&XL16, g_XL16);
    cudaGetSymbolAddress((void**)&W16,  g_W16);
    cudaGetSymbolAddress((void**)&Q16,  g_Q16);
    cudaGetSymbolAddress((void**)&K16,  g_K16);
    cudaGetSymbolAddress((void**)&V16,  g_V16);
    cudaGetSymbolAddress((void**)&AH16, g_AH16);
    cudaGetSymbolAddress((void**)&AL16, g_AL16);

    cudaFuncSetAttribute(gemm_proj,
                         cudaFuncAttributeMaxDynamicSharedMemorySize, G_SMEM);
    cudaFuncSetAttribute(gemm_out,
                         cudaFuncAttributeMaxDynamicSharedMemorySize, G_SMEM);
    cudaFuncSetAttribute(attn_tc,
                         cudaFuncAttributeMaxDynamicSharedMemorySize, AT_SMEM);

    dim3 blk(256);
    const int nX = NELEM / 4, nW = WELEM / 4;

    // Preprocess: x -> fp16 hi/lo split; W -> fp16 convert.  One launch.
    SplitBatch sp;
    const float* xs[3] = {xQ, xK, xV};
    const float* ws[4] = {Wq, Wk, Wv, Wo};
    for (int z = 0; z < 3; z++) {
        sp.src[z] = xs[z];
        sp.hi[z]  = XH16 + (size_t)z * NELEM;
        sp.lo[z]  = XL16 + (size_t)z * NELEM;
        sp.n4[z]  = nX;
        sp.mode[z] = 0;
    }
    for (int z = 3; z < 7; z++) {
        sp.src[z] = ws[z - 3];
        sp.hi[z]  = W16 + (size_t)(z - 3) * WELEM;
        sp.lo[z]  = nullptr;
        sp.n4[z]  = nW;
        sp.mode[z] = 1;
    }
    split_all<<<dim3((nX + 255) / 256, 7), blk>>>(sp);

    // 3 projection GEMMs in one launch
    GemmBatch gb;
    __half* couts[3] = {Q16, K16, V16};
    const float* biases[3] = {bq, bk, bv};
    for (int z = 0; z < 3; z++) {
        gb.Ah[z] = XH16 + (size_t)z * NELEM;
        gb.Al[z] = XL16 + (size_t)z * NELEM;
        gb.W[z]  = W16 + (size_t)z * WELEM;
        gb.bias[z] = biases[z];
        gb.C16[z] = couts[z];
        gb.scale[z] = (z == 0) ? 0.125f : 1.0f;
    }
    gemm_proj<<<dim3(DD / 128, MTOT / 128, 3), blk, G_SMEM>>>(gb);

    // Attention
    dim3 agrid(SS / 128, HH, BB);           // (16, 16, 4)
    attn_tc<<<agrid, blk, AT_SMEM>>>(Q16, K16, V16, AH16, AL16);

    // out = AO Wo^T + bo  (fp32)
    gemm_out<<<dim3(DD / 128, MTOT / 128), blk, G_SMEM>>>(
        AH16, AL16, W16 + (size_t)3 * WELEM, bo, out);
}